// round 14
// baseline (speedup 1.0000x reference)
#include <cuda_runtime.h>
#include <math.h>

#define E_   1152
#define H_   16
#define HD_  72
#define HD2_ 36
#define FF_  4304
#define FFP_ 4352          // padded (multiple of 64/128)
#define B_   32
#define S_   256
#define NT_  (B_*S_)
#define QKVW 3456

// ---------------- scratch --------------------------------------------------
__device__ float g_xn  [NT_*E_];
__device__ float g_qkv [NT_*QKVW];
__device__ float g_attn[NT_*E_];
__device__ float g_h   [NT_*E_];
__device__ float g_yn  [NT_*E_];
__device__ float g_ff  [NT_*FFP_];
__device__ float g_wqkv[QKVW*E_];
__device__ float g_bqkv[QKVW];
__device__ float g_wo[E_*E_];
__device__ float g_w1[FF_*E_];
__device__ float g_w2[E_*FFP_];

__device__ __forceinline__ unsigned f2tf(float f) {
    unsigned u; asm("cvt.rna.tf32.f32 %0, %1;" : "=r"(u) : "f"(f)); return u;
}
__device__ __forceinline__ float f2tff(float f) {
    return __uint_as_float(f2tf(f));
}

// ---------------- merged prolog kernels -------------------------------------
#define SEG_EE4   (E_*E_/4)
#define PREP_N4   (4*SEG_EE4 + FF_*E_/4)
__global__ void prep_weights(const float4* __restrict__ Wq,
                             const float4* __restrict__ Wk,
                             const float4* __restrict__ Wv,
                             const float4* __restrict__ Wo,
                             const float4* __restrict__ W1) {
    for (int i = blockIdx.x * 256 + threadIdx.x; i < PREP_N4;
         i += gridDim.x * 256) {
        const float4* src; float4* dst;
        if (i < 3 * SEG_EE4) {
            int seg = i / SEG_EE4, off = i - seg * SEG_EE4;
            src = (seg == 0 ? Wq : seg == 1 ? Wk : Wv) + off;
            dst = (float4*)g_wqkv + i;
        } else if (i < 4 * SEG_EE4) {
            src = Wo + (i - 3 * SEG_EE4);
            dst = (float4*)g_wo + (i - 3 * SEG_EE4);
        } else {
            src = W1 + (i - 4 * SEG_EE4);
            dst = (float4*)g_w1 + (i - 4 * SEG_EE4);
        }
        float4 v = *src;
        *dst = make_float4(f2tff(v.x), f2tff(v.y), f2tff(v.z), f2tff(v.w));
    }
}
#define MISC_N (E_*FFP_ + NT_*48 + QKVW)
__global__ void prep_misc(const float* __restrict__ f2w,
                          const float* __restrict__ bq,
                          const float* __restrict__ bk,
                          const float* __restrict__ bv) {
    for (int i = blockIdx.x * 256 + threadIdx.x; i < MISC_N;
         i += gridDim.x * 256) {
        if (i < E_ * FFP_) {
            int r = i / FFP_, c = i - r * FFP_;
            g_w2[i] = c < FF_ ? f2tff(f2w[r * FF_ + c]) : 0.f;
        } else if (i < E_ * FFP_ + NT_ * 48) {
            int j = i - E_ * FFP_;
            int r = j / 48, c = j - (j / 48) * 48;
            g_ff[(size_t)r * FFP_ + FF_ + c] = 0.f;
        } else {
            int j = i - E_ * FFP_ - NT_ * 48;
            g_bqkv[j] = j < E_ ? bq[j] : (j < 2 * E_ ? bk[j - E_] : bv[j - 2 * E_]);
        }
    }
}

// ---------------- RMSNorm (tf32-rounded output) -----------------------------
__global__ void rmsnorm_kernel(const float* __restrict__ x,
                               const float* __restrict__ w,
                               float* __restrict__ out, float eps) {
    int t = blockIdx.x;
    const float* xr = x + (size_t)t * E_;
    float ss = 0.f;
    for (int e = threadIdx.x; e < E_; e += 256) { float v = xr[e]; ss += v * v; }
    __shared__ float red[8];
    #pragma unroll
    for (int o = 16; o > 0; o >>= 1) ss += __shfl_xor_sync(0xffffffffu, ss, o);
    if ((threadIdx.x & 31) == 0) red[threadIdx.x >> 5] = ss;
    __syncthreads();
    if (threadIdx.x < 8) {
        float v = red[threadIdx.x];
        #pragma unroll
        for (int o = 4; o > 0; o >>= 1) v += __shfl_xor_sync(0xffu, v, o);
        if (threadIdx.x == 0) red[0] = v;
    }
    __syncthreads();
    float scale = rsqrtf(red[0] / (float)E_ + eps);
    float* outr = out + (size_t)t * E_;
    for (int e = threadIdx.x; e < E_; e += 256)
        outr[e] = f2tff(xr[e] * scale * w[e]);
}

// ---------------- TF32 GEMM: 256x128 tile, BK=64, 2-stage, 512 thr ----------
#define BKg 64
#define PADg 68
#define STGS 2
#define ASTAGE (256*PADg)
#define BSTAGE (128*PADg)
#define GSMEM ((STGS*(ASTAGE+BSTAGE))*4)

__device__ __forceinline__ void cpa16(unsigned dst, const void* src) {
    asm volatile("cp.async.cg.shared.global [%0], [%1], 16;\n" :: "r"(dst), "l"(src));
}
__device__ __forceinline__ void ldsm4(unsigned& r0, unsigned& r1,
                                      unsigned& r2, unsigned& r3,
                                      const float* p) {
    unsigned a = (unsigned)__cvta_generic_to_shared(p);
    asm volatile("ldmatrix.sync.aligned.m8n8.x4.shared.b16 {%0,%1,%2,%3}, [%4];"
                 : "=r"(r0), "=r"(r1), "=r"(r2), "=r"(r3) : "r"(a));
}
__device__ __forceinline__ void ldsm2(unsigned& r0, unsigned& r1,
                                      const float* p) {
    unsigned a = (unsigned)__cvta_generic_to_shared(p);
    asm volatile("ldmatrix.sync.aligned.m8n8.x2.shared.b16 {%0,%1}, [%2];"
                 : "=r"(r0), "=r"(r1) : "r"(a));
}

#define MMA_TF32(ACC, AF, B0, B1)                                         \
    asm volatile(                                                         \
        "mma.sync.aligned.m16n8k8.row.col.f32.tf32.tf32.f32 "             \
        "{%0,%1,%2,%3}, {%4,%5,%6,%7}, {%8,%9}, {%0,%1,%2,%3};"           \
        : "+f"((ACC)[0]), "+f"((ACC)[1]), "+f"((ACC)[2]), "+f"((ACC)[3])  \
        : "r"((AF)[0]), "r"((AF)[1]), "r"((AF)[2]), "r"((AF)[3]),         \
          "r"(B0), "r"(B1))

template<int GELU, int RES, int RND>
__global__ void __launch_bounds__(512, 1)
gemm256(const float* __restrict__ A, int lda,
        const float* __restrict__ W, const float* __restrict__ bias,
        const float* __restrict__ res, float* __restrict__ C, int ldc,
        int M, int N, int K) {
    extern __shared__ float sm[];
    float* As = sm;
    float* Bs = sm + STGS * ASTAGE;

    int t = threadIdx.x, lane = t & 31, warp = t >> 5;
    int wm = warp & 3, wn = warp >> 2;          // 4 (M) x 4 (N) warps
    int g = lane >> 2, tg = lane & 3;
    int m0 = blockIdx.y * 256, n0 = blockIdx.x * 128;

    int alr = lane & 15, alc = (lane >> 4) * 4;
    int btile = lane >> 3;
    int blr = (btile >> 1) * 8 + (lane & 7), blc = (btile & 1) * 4;

    // cp.async maps: A 256x64 (8 per thread), B 128x64 (4 per thread)
    int rowA_[8], colA_[8];
    #pragma unroll
    for (int r = 0; r < 8; r++) {
        int c = t + r * 512;
        rowA_[r] = c >> 4; colA_[r] = (c & 15) * 4;
    }
    int rowB_[4], colB_[4], nB_[4];
    #pragma unroll
    for (int r = 0; r < 4; r++) {
        int c = t + r * 512;
        rowB_[r] = c >> 4; colB_[r] = (c & 15) * 4;
        nB_[r] = min(n0 + rowB_[r], N - 1);
    }

    float acc[4][4][4];                          // 64x32 warp tile
    #pragma unroll
    for (int i = 0; i < 4; i++)
        #pragma unroll
        for (int j = 0; j < 4; j++)
            #pragma unroll
            for (int c = 0; c < 4; c++) acc[i][j][c] = 0.f;

    const int KT = K / BKg;

    auto issue = [&](int kt) {
        int st = kt & 1;
        int kk = kt * BKg;
        unsigned as = (unsigned)__cvta_generic_to_shared(As + st * ASTAGE);
        unsigned bs = (unsigned)__cvta_generic_to_shared(Bs + st * BSTAGE);
        #pragma unroll
        for (int r = 0; r < 8; r++)
            cpa16(as + (rowA_[r] * PADg + colA_[r]) * 4,
                  A + (size_t)(m0 + rowA_[r]) * lda + kk + colA_[r]);
        #pragma unroll
        for (int r = 0; r < 4; r++)
            cpa16(bs + (rowB_[r] * PADg + colB_[r]) * 4,
                  W + (size_t)nB_[r] * K + kk + colB_[r]);
        asm volatile("cp.async.commit_group;\n" ::: "memory");
    };

    issue(0);
    asm volatile("cp.async.wait_group 0;\n" ::: "memory");
    __syncthreads();

    for (int kt = 0; kt < KT; kt++) {
        if (kt + 1 < KT) issue(kt + 1);

        const float* as = As + (kt & 1) * ASTAGE + (wm * 64 + alr) * PADg + alc;
        const float* bs = Bs + (kt & 1) * BSTAGE + (wn * 32 + blr) * PADg + blc;
        #pragma unroll
        for (int h = 0; h < 8; h++) {
            int kb = h * 8;
            unsigned af[4][4], bf[2][4];
            #pragma unroll
            for (int mt = 0; mt < 4; mt++)
                ldsm4(af[mt][0], af[mt][1], af[mt][2], af[mt][3],
                      as + mt * 16 * PADg + kb);
            #pragma unroll
            for (int np = 0; np < 2; np++)
                ldsm4(bf[np][0], bf[np][1], bf[np][2], bf[np][3],
                      bs + np * 16 * PADg + kb);
            #pragma unroll
            for (int mt = 0; mt < 4; mt++)
                #pragma unroll
                for (int nt = 0; nt < 4; nt++)
                    MMA_TF32(acc[mt][nt], af[mt],
                             bf[nt >> 1][(nt & 1) * 2], bf[nt >> 1][(nt & 1) * 2 + 1]);
        }

        asm volatile("cp.async.wait_group 0;\n" ::: "memory");
        __syncthreads();
    }

    #pragma unroll
    for (int mt = 0; mt < 4; mt++) {
        int row0 = m0 + wm * 64 + mt * 16 + g;
        int row1 = row0 + 8;
        #pragma unroll
        for (int nt = 0; nt < 4; nt++) {
            int col = n0 + wn * 32 + nt * 8 + tg * 2;
            if (col < N) {
                float b0 = bias[col], b1 = bias[col + 1];
                float v00 = acc[mt][nt][0] + b0, v01 = acc[mt][nt][1] + b1;
                float v10 = acc[mt][nt][2] + b0, v11 = acc[mt][nt][3] + b1;
                if (GELU) {
                    float u;
                    u = 0.7978845608028654f * (v00 + 0.044715f * v00 * v00 * v00);
                    v00 = 0.5f * v00 * (1.f + tanhf(u));
                    u = 0.7978845608028654f * (v01 + 0.044715f * v01 * v01 * v01);
                    v01 = 0.5f * v01 * (1.f + tanhf(u));
                    u = 0.7978845608028654f * (v10 + 0.044715f * v10 * v10 * v10);
                    v10 = 0.5f * v10 * (1.f + tanhf(u));
                    u = 0.7978845608028654f * (v11 + 0.044715f * v11 * v11 * v11);
                    v11 = 0.5f * v11 * (1.f + tanhf(u));
                }
                if (RES) {
                    v00 += res[(size_t)row0 * ldc + col];
                    v01 += res[(size_t)row0 * ldc + col + 1];
                    v10 += res[(size_t)row1 * ldc + col];
                    v11 += res[(size_t)row1 * ldc + col + 1];
                }
                if (RND) {
                    v00 = f2tff(v00); v01 = f2tff(v01);
                    v10 = f2tff(v10); v11 = f2tff(v11);
                }
                C[(size_t)row0 * ldc + col]     = v00;
                C[(size_t)row0 * ldc + col + 1] = v01;
                C[(size_t)row1 * ldc + col]     = v10;
                C[(size_t)row1 * ldc + col + 1] = v11;
            }
        }
    }
}

// ---------------- Differential attention: no-max softmax --------------------
#define KW 44
#define VSTW 260
#define PW 36
#define ATT_SMEM ((256*KW + 72*VSTW + 256*72 + 16*16*PW) * 4)

__global__ void __launch_bounds__(512, 1)
diffattn_mma(const float* __restrict__ qkv,
             const float* __restrict__ lq1, const float* __restrict__ lk1,
             const float* __restrict__ lq2, const float* __restrict__ lk2,
             const float* __restrict__ subw, float* __restrict__ out) {
    extern __shared__ __align__(16) float sma[];
    float* Ks  = sma;
    float* Vst = Ks + 256 * KW;
    float* O0  = Vst + 72 * VSTW;
    float* Pw  = O0 + 256 * 72;

    int b = blockIdx.x >> 4, h = blockIdx.x & 15;
    int tid = threadIdx.x, lane = tid & 31, warp = tid >> 5;
    int g = lane >> 2, tg = lane & 3;
    size_t base = (size_t)b * S_ * QKVW;
    int coff = h * HD_;

    int alr = lane & 15, alc = (lane >> 4) * 4;
    int btile = lane >> 3;
    int blr = (btile >> 1) * 8 + (lane & 7), blc = (btile & 1) * 4;
    int tlr = lane & 7, tlc = ((lane >> 3) & 1) * 4;

    float s1 = 0.f, s2 = 0.f;
    #pragma unroll
    for (int i = 0; i < HD2_; i++) { s1 += lq1[i] * lk1[i]; s2 += lq2[i] * lk2[i]; }
    const float lambda_init = 0.8f - 0.6f * expf(-3.3f);
    const float lambda = expf(s1) - expf(s2) + lambda_init;
    const float oscale = 1.0f - lambda_init;
    const float iscale = rsqrtf(72.f);

    for (int e = tid; e < 256 * 72; e += 512) {
        int s = e / 72, d = e - s * 72;
        Vst[d * VSTW + s] = qkv[base + (size_t)s * QKVW + 2 * E_ + coff + d];
    }

    float* myP = Pw + warp * 16 * PW;
    int qrow0 = warp * 16;

    for (int sub = 0; sub < 2; sub++) {
        __syncthreads();
        for (int e = tid; e < 256 * KW; e += 512) {
            int s = e / KW, kk = e - s * KW;
            Ks[s * KW + kk] = kk < HD2_
                ? qkv[base + (size_t)s * QKVW + E_ + coff + sub * HD2_ + kk] : 0.f;
        }
        __syncthreads();

        unsigned qf[5][4];
        const float* qp = qkv + base + (size_t)qrow0 * QKVW + coff + sub * HD2_;
        #pragma unroll
        for (int kc = 0; kc < 5; kc++) {
            int kb = kc * 8;
            qf[kc][0] = __float_as_uint(qp[(size_t)g * QKVW + kb + tg]);
            qf[kc][1] = __float_as_uint(qp[(size_t)(g + 8) * QKVW + kb + tg]);
            int k4 = kb + tg + 4;
            qf[kc][2] = k4 < HD2_ ? __float_as_uint(qp[(size_t)g * QKVW + k4]) : 0u;
            qf[kc][3] = k4 < HD2_ ? __float_as_uint(qp[(size_t)(g + 8) * QKVW + k4]) : 0u;
        }

        float zr0 = 0.f, zr1 = 0.f;
        float oc[9][4];
        #pragma unroll
        for (int vt = 0; vt < 9; vt++)
            #pragma unroll
            for (int c = 0; c < 4; c++) oc[vt][c] = 0.f;

        for (int ch = 0; ch < 8; ch++) {
            float sc[4][4];
            #pragma unroll
            for (int nt = 0; nt < 4; nt++)
                #pragma unroll
                for (int c = 0; c < 4; c++) sc[nt][c] = 0.f;

            const float* kbase = Ks + (ch * 32 + blr) * KW + blc;
            #pragma unroll
            for (int kc = 0; kc < 5; kc++) {
                int kb = kc * 8;
                unsigned bf[2][4];
                #pragma unroll
                for (int half = 0; half < 2; half++)
                    ldsm4(bf[half][0], bf[half][1], bf[half][2], bf[half][3],
                          kbase + half * 16 * KW + kb);
                #pragma unroll
                for (int nt = 0; nt < 4; nt++)
                    MMA_TF32(sc[nt], qf[kc],
                             bf[nt >> 1][(nt & 1) * 2],
                             bf[nt >> 1][(nt & 1) * 2 + 1]);
            }

            #pragma unroll
            for (int nt = 0; nt < 4; nt++) {
                float e0 = __expf(sc[nt][0] * iscale);
                float e1 = __expf(sc[nt][1] * iscale);
                float e2 = __expf(sc[nt][2] * iscale);
                float e3 = __expf(sc[nt][3] * iscale);
                zr0 += e0 + e1;
                zr1 += e2 + e3;
                int c0 = nt * 8 + 2 * tg;
                *(float2*)&myP[g * PW + c0]       = make_float2(f2tff(e0), f2tff(e1));
                *(float2*)&myP[(g + 8) * PW + c0] = make_float2(f2tff(e2), f2tff(e3));
            }
            __syncwarp();

            #pragma unroll
            for (int kc = 0; kc < 4; kc++) {
                int kb = kc * 8;
                unsigned pa[4];
                ldsm4(pa[0], pa[1], pa[2], pa[3], myP + alr * PW + kb + alc);
                const float* vb0 = Vst + blr * VSTW + ch * 32 + kb + blc;
                #pragma unroll
                for (int g4 = 0; g4 < 4; g4++) {
                    unsigned vb[4];
                    ldsm4(vb[0], vb[1], vb[2], vb[3], vb0 + g4 * 16 * VSTW);
                    MMA_TF32(oc[g4 * 2],     pa, vb[0], vb[1]);
                    MMA_TF32(oc[g4 * 2 + 1], pa, vb[2], vb[3]);
                }
                unsigned t0, t1;
                ldsm2(t0, t1, Vst + (64 + tlr) * VSTW + ch * 32 + kb + tlc);
                MMA_TF32(oc[8], pa, t0, t1);
            }
            __syncwarp();
        }

        zr0 += __shfl_xor_sync(0xffffffffu, zr0, 1);
        zr0 += __shfl_xor_sync(0xffffffffu, zr0, 2);
        zr1 += __shfl_xor_sync(0xffffffffu, zr1, 1);
        zr1 += __shfl_xor_sync(0xffffffffu, zr1, 2);
        float iz0 = 1.f / zr0, iz1 = 1.f / zr1;

        if (sub == 0) {
            #pragma unroll
            for (int vt = 0; vt < 9; vt++) {
                int c0 = vt * 8 + 2 * tg;
                *(float2*)&O0[(qrow0 + g) * 72 + c0] =
                    make_float2(oc[vt][0] * iz0, oc[vt][1] * iz0);
                *(float2*)&O0[(qrow0 + g + 8) * 72 + c0] =
                    make_float2(oc[vt][2] * iz1, oc[vt][3] * iz1);
            }
        } else {
            float cr[9][4];
            float ss0 = 0.f, ss1 = 0.f;
            #pragma unroll
            for (int vt = 0; vt < 9; vt++) {
                int c0 = vt * 8 + 2 * tg;
                float2 p0 = *(const float2*)&O0[(qrow0 + g) * 72 + c0];
                float2 p1 = *(const float2*)&O0[(qrow0 + g + 8) * 72 + c0];
                cr[vt][0] = p0.x - lambda * oc[vt][0] * iz0;
                cr[vt][1] = p0.y - lambda * oc[vt][1] * iz0;
                cr[vt][2] = p1.x - lambda * oc[vt][2] * iz1;
                cr[vt][3] = p1.y - lambda * oc[vt][3] * iz1;
                ss0 += cr[vt][0] * cr[vt][0] + cr[vt][1] * cr[vt][1];
                ss1 += cr[vt][2] * cr[vt][2] + cr[vt][3] * cr[vt][3];
            }
            ss0 += __shfl_xor_sync(0xffffffffu, ss0, 1);
            ss0 += __shfl_xor_sync(0xffffffffu, ss0, 2);
            ss1 += __shfl_xor_sync(0xffffffffu, ss1, 1);
            ss1 += __shfl_xor_sync(0xffffffffu, ss1, 2);
            float sc0 = rsqrtf(ss0 / 72.f + 1e-5f) * oscale;
            float sc1 = rsqrtf(ss1 / 72.f + 1e-5f) * oscale;
            float* o0p = out + (size_t)(b * S_ + qrow0 + g) * E_ + coff;
            float* o1p = out + (size_t)(b * S_ + qrow0 + g + 8) * E_ + coff;
            #pragma unroll
            for (int vt = 0; vt < 9; vt++) {
                int c0 = vt * 8 + 2 * tg;
                float w0 = subw[c0], w1 = subw[c0 + 1];
                *(float2*)&o0p[c0] =
                    make_float2(f2tff(cr[vt][0] * sc0 * w0),
                                f2tff(cr[vt][1] * sc0 * w1));
                *(float2*)&o1p[c0] =
                    make_float2(f2tff(cr[vt][2] * sc1 * w0),
                                f2tff(cr[vt][3] * sc1 * w1));
            }
        }
    }
}

// ---------------- host launch ---------------------------------------------
extern "C" void kernel_launch(void* const* d_in, const int* in_sizes, int n_in,
                              void* d_out, int out_size) {
    const float* hs   = (const float*)d_in[0];
    const float* Wq   = (const float*)d_in[1];
    const float* bq   = (const float*)d_in[2];
    const float* Wk   = (const float*)d_in[3];
    const float* bk   = (const float*)d_in[4];
    const float* Wv   = (const float*)d_in[5];
    const float* bv   = (const float*)d_in[6];
    const float* Wo   = (const float*)d_in[7];
    const float* bo   = (const float*)d_in[8];
    const float* lq1  = (const float*)d_in[9];
    const float* lk1  = (const float*)d_in[10];
    const float* lq2  = (const float*)d_in[11];
    const float* lk2  = (const float*)d_in[12];
    const float* subw = (const float*)d_in[13];
    const float* r1w  = (const float*)d_in[14];
    const float* r2w  = (const float*)d_in[15];
    const float* f1w  = (const float*)d_in[16];
    const float* f1b  = (const float*)d_in[17];
    const float* f2w  = (const float*)d_in[18];
    const float* f2b  = (const float*)d_in[19];

    float *xn, *qkvb, *at, *hb, *yn, *ff;
    float *wqkv, *bqkv, *wo, *w1, *w2;
    cudaGetSymbolAddress((void**)&xn,   g_xn);
    cudaGetSymbolAddress((void**)&qkvb, g_qkv);
    cudaGetSymbolAddress((void**)&at,   g_attn);
    cudaGetSymbolAddress((void**)&hb,   g_h);
    cudaGetSymbolAddress((void**)&yn,   g_yn);
    cudaGetSymbolAddress((void**)&ff,   g_ff);
    cudaGetSymbolAddress((void**)&wqkv, g_wqkv);
    cudaGetSymbolAddress((void**)&bqkv, g_bqkv);
    cudaGetSymbolAddress((void**)&wo,   g_wo);
    cudaGetSymbolAddress((void**)&w1,   g_w1);
    cudaGetSymbolAddress((void**)&w2,   g_w2);

    cudaFuncSetAttribute(diffattn_mma,
                         cudaFuncAttributeMaxDynamicSharedMemorySize, ATT_SMEM);
    cudaFuncSetAttribute(gemm256<0,0,1>,
                         cudaFuncAttributeMaxDynamicSharedMemorySize, GSMEM);
    cudaFuncSetAttribute(gemm256<0,1,0>,
                         cudaFuncAttributeMaxDynamicSharedMemorySize, GSMEM);
    cudaFuncSetAttribute(gemm256<1,0,1>,
                         cudaFuncAttributeMaxDynamicSharedMemorySize, GSMEM);

    prep_weights<<<1184, 256>>>((const float4*)Wq, (const float4*)Wk,
                                (const float4*)Wv, (const float4*)Wo,
                                (const float4*)f1w);
    prep_misc<<<1184, 256>>>(f2w, bq, bk, bv);

    dim3 gqkv(27, 32), g9(9, 32), g34(34, 32);

    rmsnorm_kernel<<<NT_, 256>>>(hs, r1w, xn, 1e-6f);
    gemm256<0,0,1><<<gqkv, 512, GSMEM>>>(xn, E_, wqkv, bqkv, nullptr,
                                         qkvb, QKVW, NT_, QKVW, E_);
    diffattn_mma<<<B_*H_, 512, ATT_SMEM>>>(qkvb, lq1, lk1, lq2, lk2, subw, at);
    gemm256<0,1,0><<<g9, 512, GSMEM>>>(at, E_, wo, bo, hs, hb, E_, NT_, E_, E_);
    rmsnorm_kernel<<<NT_, 256>>>(hb, r2w, yn, 1e-6f);
    gemm256<1,0,1><<<g34, 512, GSMEM>>>(yn, E_, w1, f1b, nullptr, ff, FFP_,
                                        NT_, FF_, E_);
    gemm256<0,1,0><<<g9, 512, GSMEM>>>(ff, FFP_, w2, f2b, hb, (float*)d_out, E_,
                                       NT_, E_, FFP_);
}

// round 15
// speedup vs baseline: 1.0768x; 1.0768x over previous
#include <cuda_runtime.h>
#include <math.h>

#define E_   1152
#define H_   16
#define HD_  72
#define HD2_ 36
#define FF_  4304
#define FFP_ 4320
#define B_   32
#define S_   256
#define NT_  (B_*S_)
#define QKVW 3456

// ---------------- scratch --------------------------------------------------
__device__ float g_xn  [NT_*E_];
__device__ float g_qkv [NT_*QKVW];
__device__ float g_attn[NT_*E_];
__device__ float g_h   [NT_*E_];
__device__ float g_yn  [NT_*E_];
__device__ float g_ff  [NT_*FFP_];
__device__ float g_wqkv[QKVW*E_];
__device__ float g_bqkv[QKVW];
__device__ float g_wo[E_*E_];
__device__ float g_w1[FF_*E_];
__device__ float g_w2[E_*FFP_];

__device__ __forceinline__ unsigned f2tf(float f) {
    unsigned u; asm("cvt.rna.tf32.f32 %0, %1;" : "=r"(u) : "f"(f)); return u;
}
__device__ __forceinline__ float f2tff(float f) {
    return __uint_as_float(f2tf(f));
}

// ---------------- merged prolog kernels -------------------------------------
#define SEG_EE4   (E_*E_/4)
#define PREP_N4   (4*SEG_EE4 + FF_*E_/4)
__global__ void prep_weights(const float4* __restrict__ Wq,
                             const float4* __restrict__ Wk,
                             const float4* __restrict__ Wv,
                             const float4* __restrict__ Wo,
                             const float4* __restrict__ W1) {
    for (int i = blockIdx.x * 256 + threadIdx.x; i < PREP_N4;
         i += gridDim.x * 256) {
        const float4* src; float4* dst;
        if (i < 3 * SEG_EE4) {
            int seg = i / SEG_EE4, off = i - seg * SEG_EE4;
            src = (seg == 0 ? Wq : seg == 1 ? Wk : Wv) + off;
            dst = (float4*)g_wqkv + i;
        } else if (i < 4 * SEG_EE4) {
            src = Wo + (i - 3 * SEG_EE4);
            dst = (float4*)g_wo + (i - 3 * SEG_EE4);
        } else {
            src = W1 + (i - 4 * SEG_EE4);
            dst = (float4*)g_w1 + (i - 4 * SEG_EE4);
        }
        float4 v = *src;
        *dst = make_float4(f2tff(v.x), f2tff(v.y), f2tff(v.z), f2tff(v.w));
    }
}
#define MISC_N (E_*FFP_ + NT_*16 + QKVW)
__global__ void prep_misc(const float* __restrict__ f2w,
                          const float* __restrict__ bq,
                          const float* __restrict__ bk,
                          const float* __restrict__ bv) {
    for (int i = blockIdx.x * 256 + threadIdx.x; i < MISC_N;
         i += gridDim.x * 256) {
        if (i < E_ * FFP_) {
            int r = i / FFP_, c = i - r * FFP_;
            g_w2[i] = c < FF_ ? f2tff(f2w[r * FF_ + c]) : 0.f;
        } else if (i < E_ * FFP_ + NT_ * 16) {
            int j = i - E_ * FFP_;
            int r = j >> 4, c = j & 15;
            g_ff[(size_t)r * FFP_ + FF_ + c] = 0.f;
        } else {
            int j = i - E_ * FFP_ - NT_ * 16;
            g_bqkv[j] = j < E_ ? bq[j] : (j < 2 * E_ ? bk[j - E_] : bv[j - 2 * E_]);
        }
    }
}

// ---------------- RMSNorm (tf32-rounded output) -----------------------------
__global__ void rmsnorm_kernel(const float* __restrict__ x,
                               const float* __restrict__ w,
                               float* __restrict__ out, float eps) {
    int t = blockIdx.x;
    const float* xr = x + (size_t)t * E_;
    float ss = 0.f;
    for (int e = threadIdx.x; e < E_; e += 256) { float v = xr[e]; ss += v * v; }
    __shared__ float red[8];
    #pragma unroll
    for (int o = 16; o > 0; o >>= 1) ss += __shfl_xor_sync(0xffffffffu, ss, o);
    if ((threadIdx.x & 31) == 0) red[threadIdx.x >> 5] = ss;
    __syncthreads();
    if (threadIdx.x < 8) {
        float v = red[threadIdx.x];
        #pragma unroll
        for (int o = 4; o > 0; o >>= 1) v += __shfl_xor_sync(0xffu, v, o);
        if (threadIdx.x == 0) red[0] = v;
    }
    __syncthreads();
    float scale = rsqrtf(red[0] / (float)E_ + eps);
    float* outr = out + (size_t)t * E_;
    for (int e = threadIdx.x; e < E_; e += 256)
        outr[e] = f2tff(xr[e] * scale * w[e]);
}

// ---------------- TF32 GEMM: 256x128 tile, BK=32, 3 stages, 512 thr ---------
#define BKg 32
#define PADg 36
#define STGS 3
#define ASTAGE (256*PADg)
#define BSTAGE (128*PADg)
#define GSMEM ((STGS*(ASTAGE+BSTAGE))*4)

__device__ __forceinline__ void cpa16(unsigned dst, const void* src) {
    asm volatile("cp.async.cg.shared.global [%0], [%1], 16;\n" :: "r"(dst), "l"(src));
}
__device__ __forceinline__ void ldsm4(unsigned& r0, unsigned& r1,
                                      unsigned& r2, unsigned& r3,
                                      const float* p) {
    unsigned a = (unsigned)__cvta_generic_to_shared(p);
    asm volatile("ldmatrix.sync.aligned.m8n8.x4.shared.b16 {%0,%1,%2,%3}, [%4];"
                 : "=r"(r0), "=r"(r1), "=r"(r2), "=r"(r3) : "r"(a));
}
__device__ __forceinline__ void ldsm2(unsigned& r0, unsigned& r1,
                                      const float* p) {
    unsigned a = (unsigned)__cvta_generic_to_shared(p);
    asm volatile("ldmatrix.sync.aligned.m8n8.x2.shared.b16 {%0,%1}, [%2];"
                 : "=r"(r0), "=r"(r1) : "r"(a));
}

#define MMA_TF32(ACC, AF, B0, B1)                                         \
    asm volatile(                                                         \
        "mma.sync.aligned.m16n8k8.row.col.f32.tf32.tf32.f32 "             \
        "{%0,%1,%2,%3}, {%4,%5,%6,%7}, {%8,%9}, {%0,%1,%2,%3};"           \
        : "+f"((ACC)[0]), "+f"((ACC)[1]), "+f"((ACC)[2]), "+f"((ACC)[3])  \
        : "r"((AF)[0]), "r"((AF)[1]), "r"((AF)[2]), "r"((AF)[3]),         \
          "r"(B0), "r"(B1))

__device__ __forceinline__ float gelu_fast(float v) {
    float u = 0.7978845608028654f * (v + 0.044715f * v * v * v);
    // 0.5*(1+tanh(u)) == sigmoid(2u)
    return v / (1.f + __expf(-2.f * u));
}

template<int GELU, int RES, int RND>
__global__ void __launch_bounds__(512, 1)
gemm256(const float* __restrict__ A, int lda,
        const float* __restrict__ W, const float* __restrict__ bias,
        const float* __restrict__ res, float* __restrict__ C, int ldc,
        int M, int N, int K) {
    extern __shared__ float sm[];
    float* As = sm;
    float* Bs = sm + STGS * ASTAGE;

    int t = threadIdx.x, lane = t & 31, warp = t >> 5;
    int wm = warp & 3, wn = warp >> 2;          // 4 (M) x 4 (N) warps
    int g = lane >> 2, tg = lane & 3;
    int m0 = blockIdx.y * 256, n0 = blockIdx.x * 128;

    int alr = lane & 15, alc = (lane >> 4) * 4;
    int btile = lane >> 3;
    int blr = (btile >> 1) * 8 + (lane & 7), blc = (btile & 1) * 4;

    int rowA_[4], colA_[4];
    #pragma unroll
    for (int r = 0; r < 4; r++) {
        int c = t + r * 512;
        rowA_[r] = c >> 3; colA_[r] = (c & 7) * 4;
    }
    int rowB_[2], colB_[2], nB_[2];
    #pragma unroll
    for (int r = 0; r < 2; r++) {
        int c = t + r * 512;
        rowB_[r] = c >> 3; colB_[r] = (c & 7) * 4;
        nB_[r] = min(n0 + rowB_[r], N - 1);
    }

    float acc[4][4][4];                          // 64x32 warp tile
    #pragma unroll
    for (int i = 0; i < 4; i++)
        #pragma unroll
        for (int j = 0; j < 4; j++)
            #pragma unroll
            for (int c = 0; c < 4; c++) acc[i][j][c] = 0.f;

    const int KT = K / BKg;

    auto issue = [&](int kt) {
        int st = kt % STGS;
        int kk = kt * BKg;
        unsigned as = (unsigned)__cvta_generic_to_shared(As + st * ASTAGE);
        unsigned bs = (unsigned)__cvta_generic_to_shared(Bs + st * BSTAGE);
        #pragma unroll
        for (int r = 0; r < 4; r++)
            cpa16(as + (rowA_[r] * PADg + colA_[r]) * 4,
                  A + (size_t)(m0 + rowA_[r]) * lda + kk + colA_[r]);
        #pragma unroll
        for (int r = 0; r < 2; r++)
            cpa16(bs + (rowB_[r] * PADg + colB_[r]) * 4,
                  W + (size_t)nB_[r] * K + kk + colB_[r]);
        asm volatile("cp.async.commit_group;\n" ::: "memory");
    };

    issue(0); issue(1);
    asm volatile("cp.async.wait_group 1;\n" ::: "memory");
    __syncthreads();

    for (int kt = 0; kt < KT; kt++) {
        const float* as = As + (kt % STGS) * ASTAGE + (wm * 64 + alr) * PADg + alc;
        const float* bs = Bs + (kt % STGS) * BSTAGE + (wn * 32 + blr) * PADg + blc;
        #pragma unroll
        for (int h = 0; h < 4; h++) {
            int kb = h * 8;
            unsigned af[4][4], bf[2][4];
            #pragma unroll
            for (int mt = 0; mt < 4; mt++)
                ldsm4(af[mt][0], af[mt][1], af[mt][2], af[mt][3],
                      as + mt * 16 * PADg + kb);
            #pragma unroll
            for (int np = 0; np < 2; np++)
                ldsm4(bf[np][0], bf[np][1], bf[np][2], bf[np][3],
                      bs + np * 16 * PADg + kb);
            #pragma unroll
            for (int mt = 0; mt < 4; mt++)
                #pragma unroll
                for (int nt = 0; nt < 4; nt++)
                    MMA_TF32(acc[mt][nt], af[mt],
                             bf[nt >> 1][(nt & 1) * 2], bf[nt >> 1][(nt & 1) * 2 + 1]);
        }

        if (kt + 2 < KT) {
            issue(kt + 2);
            asm volatile("cp.async.wait_group 1;\n" ::: "memory");
        } else {
            asm volatile("cp.async.wait_group 0;\n" ::: "memory");
        }
        __syncthreads();
    }

    #pragma unroll
    for (int mt = 0; mt < 4; mt++) {
        int row0 = m0 + wm * 64 + mt * 16 + g;
        int row1 = row0 + 8;
        #pragma unroll
        for (int nt = 0; nt < 4; nt++) {
            int col = n0 + wn * 32 + nt * 8 + tg * 2;
            if (col < N) {
                float b0 = bias[col], b1 = bias[col + 1];
                float v00 = acc[mt][nt][0] + b0, v01 = acc[mt][nt][1] + b1;
                float v10 = acc[mt][nt][2] + b0, v11 = acc[mt][nt][3] + b1;
                if (GELU) {
                    v00 = gelu_fast(v00); v01 = gelu_fast(v01);
                    v10 = gelu_fast(v10); v11 = gelu_fast(v11);
                }
                if (RES) {
                    v00 += res[(size_t)row0 * ldc + col];
                    v01 += res[(size_t)row0 * ldc + col + 1];
                    v10 += res[(size_t)row1 * ldc + col];
                    v11 += res[(size_t)row1 * ldc + col + 1];
                }
                if (RND) {
                    v00 = f2tff(v00); v01 = f2tff(v01);
                    v10 = f2tff(v10); v11 = f2tff(v11);
                }
                C[(size_t)row0 * ldc + col]     = v00;
                C[(size_t)row0 * ldc + col + 1] = v01;
                C[(size_t)row1 * ldc + col]     = v10;
                C[(size_t)row1 * ldc + col + 1] = v11;
            }
        }
    }
}

// ---------------- Differential attention: no-max softmax --------------------
#define KW 44
#define VSTW 260
#define PW 36
#define ATT_SMEM ((256*KW + 72*VSTW + 256*72 + 16*16*PW) * 4)

__global__ void __launch_bounds__(512, 1)
diffattn_mma(const float* __restrict__ qkv,
             const float* __restrict__ lq1, const float* __restrict__ lk1,
             const float* __restrict__ lq2, const float* __restrict__ lk2,
             const float* __restrict__ subw, float* __restrict__ out) {
    extern __shared__ __align__(16) float sma[];
    float* Ks  = sma;
    float* Vst = Ks + 256 * KW;
    float* O0  = Vst + 72 * VSTW;
    float* Pw  = O0 + 256 * 72;

    int b = blockIdx.x >> 4, h = blockIdx.x & 15;
    int tid = threadIdx.x, lane = tid & 31, warp = tid >> 5;
    int g = lane >> 2, tg = lane & 3;
    size_t base = (size_t)b * S_ * QKVW;
    int coff = h * HD_;

    int alr = lane & 15, alc = (lane >> 4) * 4;
    int btile = lane >> 3;
    int blr = (btile >> 1) * 8 + (lane & 7), blc = (btile & 1) * 4;
    int tlr = lane & 7, tlc = ((lane >> 3) & 1) * 4;

    float s1 = 0.f, s2 = 0.f;
    #pragma unroll
    for (int i = 0; i < HD2_; i++) { s1 += lq1[i] * lk1[i]; s2 += lq2[i] * lk2[i]; }
    const float lambda_init = 0.8f - 0.6f * expf(-3.3f);
    const float lambda = expf(s1) - expf(s2) + lambda_init;
    const float oscale = 1.0f - lambda_init;
    const float iscale = rsqrtf(72.f);

    for (int e = tid; e < 256 * 72; e += 512) {
        int s = e / 72, d = e - s * 72;
        Vst[d * VSTW + s] = qkv[base + (size_t)s * QKVW + 2 * E_ + coff + d];
    }

    float* myP = Pw + warp * 16 * PW;
    int qrow0 = warp * 16;

    for (int sub = 0; sub < 2; sub++) {
        __syncthreads();
        for (int e = tid; e < 256 * KW; e += 512) {
            int s = e / KW, kk = e - s * KW;
            Ks[s * KW + kk] = kk < HD2_
                ? qkv[base + (size_t)s * QKVW + E_ + coff + sub * HD2_ + kk] : 0.f;
        }
        __syncthreads();

        unsigned qf[5][4];
        const float* qp = qkv + base + (size_t)qrow0 * QKVW + coff + sub * HD2_;
        #pragma unroll
        for (int kc = 0; kc < 5; kc++) {
            int kb = kc * 8;
            qf[kc][0] = __float_as_uint(qp[(size_t)g * QKVW + kb + tg]);
            qf[kc][1] = __float_as_uint(qp[(size_t)(g + 8) * QKVW + kb + tg]);
            int k4 = kb + tg + 4;
            qf[kc][2] = k4 < HD2_ ? __float_as_uint(qp[(size_t)g * QKVW + k4]) : 0u;
            qf[kc][3] = k4 < HD2_ ? __float_as_uint(qp[(size_t)(g + 8) * QKVW + k4]) : 0u;
        }

        float zr0 = 0.f, zr1 = 0.f;
        float oc[9][4];
        #pragma unroll
        for (int vt = 0; vt < 9; vt++)
            #pragma unroll
            for (int c = 0; c < 4; c++) oc[vt][c] = 0.f;

        for (int ch = 0; ch < 8; ch++) {
            float sc[4][4];
            #pragma unroll
            for (int nt = 0; nt < 4; nt++)
                #pragma unroll
                for (int c = 0; c < 4; c++) sc[nt][c] = 0.f;

            const float* kbase = Ks + (ch * 32 + blr) * KW + blc;
            #pragma unroll
            for (int kc = 0; kc < 5; kc++) {
                int kb = kc * 8;
                unsigned bf[2][4];
                #pragma unroll
                for (int half = 0; half < 2; half++)
                    ldsm4(bf[half][0], bf[half][1], bf[half][2], bf[half][3],
                          kbase + half * 16 * KW + kb);
                #pragma unroll
                for (int nt = 0; nt < 4; nt++)
                    MMA_TF32(sc[nt], qf[kc],
                             bf[nt >> 1][(nt & 1) * 2],
                             bf[nt >> 1][(nt & 1) * 2 + 1]);
            }

            #pragma unroll
            for (int nt = 0; nt < 4; nt++) {
                float e0 = __expf(sc[nt][0] * iscale);
                float e1 = __expf(sc[nt][1] * iscale);
                float e2 = __expf(sc[nt][2] * iscale);
                float e3 = __expf(sc[nt][3] * iscale);
                zr0 += e0 + e1;
                zr1 += e2 + e3;
                int c0 = nt * 8 + 2 * tg;
                *(float2*)&myP[g * PW + c0]       = make_float2(f2tff(e0), f2tff(e1));
                *(float2*)&myP[(g + 8) * PW + c0] = make_float2(f2tff(e2), f2tff(e3));
            }
            __syncwarp();

            #pragma unroll
            for (int kc = 0; kc < 4; kc++) {
                int kb = kc * 8;
                unsigned pa[4];
                ldsm4(pa[0], pa[1], pa[2], pa[3], myP + alr * PW + kb + alc);
                const float* vb0 = Vst + blr * VSTW + ch * 32 + kb + blc;
                #pragma unroll
                for (int g4 = 0; g4 < 4; g4++) {
                    unsigned vb[4];
                    ldsm4(vb[0], vb[1], vb[2], vb[3], vb0 + g4 * 16 * VSTW);
                    MMA_TF32(oc[g4 * 2],     pa, vb[0], vb[1]);
                    MMA_TF32(oc[g4 * 2 + 1], pa, vb[2], vb[3]);
                }
                unsigned t0, t1;
                ldsm2(t0, t1, Vst + (64 + tlr) * VSTW + ch * 32 + kb + tlc);
                MMA_TF32(oc[8], pa, t0, t1);
            }
            __syncwarp();
        }

        zr0 += __shfl_xor_sync(0xffffffffu, zr0, 1);
        zr0 += __shfl_xor_sync(0xffffffffu, zr0, 2);
        zr1 += __shfl_xor_sync(0xffffffffu, zr1, 1);
        zr1 += __shfl_xor_sync(0xffffffffu, zr1, 2);
        float iz0 = 1.f / zr0, iz1 = 1.f / zr1;

        if (sub == 0) {
            #pragma unroll
            for (int vt = 0; vt < 9; vt++) {
                int c0 = vt * 8 + 2 * tg;
                *(float2*)&O0[(qrow0 + g) * 72 + c0] =
                    make_float2(oc[vt][0] * iz0, oc[vt][1] * iz0);
                *(float2*)&O0[(qrow0 + g + 8) * 72 + c0] =
                    make_float2(oc[vt][2] * iz1, oc[vt][3] * iz1);
            }
        } else {
            float cr[9][4];
            float ss0 = 0.f, ss1 = 0.f;
            #pragma unroll
            for (int vt = 0; vt < 9; vt++) {
                int c0 = vt * 8 + 2 * tg;
                float2 p0 = *(const float2*)&O0[(qrow0 + g) * 72 + c0];
                float2 p1 = *(const float2*)&O0[(qrow0 + g + 8) * 72 + c0];
                cr[vt][0] = p0.x - lambda * oc[vt][0] * iz0;
                cr[vt][1] = p0.y - lambda * oc[vt][1] * iz0;
                cr[vt][2] = p1.x - lambda * oc[vt][2] * iz1;
                cr[vt][3] = p1.y - lambda * oc[vt][3] * iz1;
                ss0 += cr[vt][0] * cr[vt][0] + cr[vt][1] * cr[vt][1];
                ss1 += cr[vt][2] * cr[vt][2] + cr[vt][3] * cr[vt][3];
            }
            ss0 += __shfl_xor_sync(0xffffffffu, ss0, 1);
            ss0 += __shfl_xor_sync(0xffffffffu, ss0, 2);
            ss1 += __shfl_xor_sync(0xffffffffu, ss1, 1);
            ss1 += __shfl_xor_sync(0xffffffffu, ss1, 2);
            float sc0 = rsqrtf(ss0 / 72.f + 1e-5f) * oscale;
            float sc1 = rsqrtf(ss1 / 72.f + 1e-5f) * oscale;
            float* o0p = out + (size_t)(b * S_ + qrow0 + g) * E_ + coff;
            float* o1p = out + (size_t)(b * S_ + qrow0 + g + 8) * E_ + coff;
            #pragma unroll
            for (int vt = 0; vt < 9; vt++) {
                int c0 = vt * 8 + 2 * tg;
                float w0 = subw[c0], w1 = subw[c0 + 1];
                *(float2*)&o0p[c0] =
                    make_float2(f2tff(cr[vt][0] * sc0 * w0),
                                f2tff(cr[vt][1] * sc0 * w1));
                *(float2*)&o1p[c0] =
                    make_float2(f2tff(cr[vt][2] * sc1 * w0),
                                f2tff(cr[vt][3] * sc1 * w1));
            }
        }
    }
}

// ---------------- host launch ---------------------------------------------
extern "C" void kernel_launch(void* const* d_in, const int* in_sizes, int n_in,
                              void* d_out, int out_size) {
    const float* hs   = (const float*)d_in[0];
    const float* Wq   = (const float*)d_in[1];
    const float* bq   = (const float*)d_in[2];
    const float* Wk   = (const float*)d_in[3];
    const float* bk   = (const float*)d_in[4];
    const float* Wv   = (const float*)d_in[5];
    const float* bv   = (const float*)d_in[6];
    const float* Wo   = (const float*)d_in[7];
    const float* bo   = (const float*)d_in[8];
    const float* lq1  = (const float*)d_in[9];
    const float* lk1  = (const float*)d_in[10];
    const float* lq2  = (const float*)d_in[11];
    const float* lk2  = (const float*)d_in[12];
    const float* subw = (const float*)d_in[13];
    const float* r1w  = (const float*)d_in[14];
    const float* r2w  = (const float*)d_in[15];
    const float* f1w  = (const float*)d_in[16];
    const float* f1b  = (const float*)d_in[17];
    const float* f2w  = (const float*)d_in[18];
    const float* f2b  = (const float*)d_in[19];

    float *xn, *qkvb, *at, *hb, *yn, *ff;
    float *wqkv, *bqkv, *wo, *w1, *w2;
    cudaGetSymbolAddress((void**)&xn,   g_xn);
    cudaGetSymbolAddress((void**)&qkvb, g_qkv);
    cudaGetSymbolAddress((void**)&at,   g_attn);
    cudaGetSymbolAddress((void**)&hb,   g_h);
    cudaGetSymbolAddress((void**)&yn,   g_yn);
    cudaGetSymbolAddress((void**)&ff,   g_ff);
    cudaGetSymbolAddress((void**)&wqkv, g_wqkv);
    cudaGetSymbolAddress((void**)&bqkv, g_bqkv);
    cudaGetSymbolAddress((void**)&wo,   g_wo);
    cudaGetSymbolAddress((void**)&w1,   g_w1);
    cudaGetSymbolAddress((void**)&w2,   g_w2);

    cudaFuncSetAttribute(diffattn_mma,
                         cudaFuncAttributeMaxDynamicSharedMemorySize, ATT_SMEM);
    cudaFuncSetAttribute(gemm256<0,0,1>,
                         cudaFuncAttributeMaxDynamicSharedMemorySize, GSMEM);
    cudaFuncSetAttribute(gemm256<0,1,0>,
                         cudaFuncAttributeMaxDynamicSharedMemorySize, GSMEM);
    cudaFuncSetAttribute(gemm256<1,0,1>,
                         cudaFuncAttributeMaxDynamicSharedMemorySize, GSMEM);

    prep_weights<<<1184, 256>>>((const float4*)Wq, (const float4*)Wk,
                                (const float4*)Wv, (const float4*)Wo,
                                (const float4*)f1w);
    prep_misc<<<1184, 256>>>(f2w, bq, bk, bv);

    dim3 gqkv(27, 32), g9(9, 32), g34(34, 32);

    rmsnorm_kernel<<<NT_, 256>>>(hs, r1w, xn, 1e-6f);
    gemm256<0,0,1><<<gqkv, 512, GSMEM>>>(xn, E_, wqkv, bqkv, nullptr,
                                         qkvb, QKVW, NT_, QKVW, E_);
    diffattn_mma<<<B_*H_, 512, ATT_SMEM>>>(qkvb, lq1, lk1, lq2, lk2, subw, at);
    gemm256<0,1,0><<<g9, 512, GSMEM>>>(at, E_, wo, bo, hs, hb, E_, NT_, E_, E_);
    rmsnorm_kernel<<<NT_, 256>>>(hb, r2w, yn, 1e-6f);
    gemm256<1,0,1><<<g34, 512, GSMEM>>>(yn, E_, w1, f1b, nullptr, ff, FFP_,
                                        NT_, FF_, E_);
    gemm256<0,1,0><<<g9, 512, GSMEM>>>(ff, FFP_, w2, f2b, hb, (float*)d_out, E_,
                                       NT_, E_, FFP_);
}

// round 16
// speedup vs baseline: 1.0774x; 1.0005x over previous
#include <cuda_runtime.h>
#include <math.h>

#define E_   1152
#define H_   16
#define HD_  72
#define HD2_ 36
#define FF_  4304
#define FFP_ 4320
#define B_   32
#define S_   256
#define NT_  (B_*S_)
#define QKVW 3456

// ---------------- scratch --------------------------------------------------
__device__ float g_xn  [NT_*E_];
__device__ float g_qkv [NT_*QKVW];
__device__ float g_attn[NT_*E_];
__device__ float g_h   [NT_*E_];
__device__ float g_yn  [NT_*E_];
__device__ float g_ff  [NT_*FFP_];
__device__ float g_wqkv[QKVW*E_];
__device__ float g_bqkv[QKVW];
__device__ float g_wo[E_*E_];
__device__ float g_w1[FF_*E_];
__device__ float g_w2[E_*FFP_];

__device__ __forceinline__ unsigned f2tf(float f) {
    unsigned u; asm("cvt.rna.tf32.f32 %0, %1;" : "=r"(u) : "f"(f)); return u;
}
__device__ __forceinline__ float f2tff(float f) {
    return __uint_as_float(f2tf(f));
}

// ---------------- merged prolog kernels -------------------------------------
#define SEG_EE4   (E_*E_/4)
#define PREP_N4   (4*SEG_EE4 + FF_*E_/4)
__global__ void prep_weights(const float4* __restrict__ Wq,
                             const float4* __restrict__ Wk,
                             const float4* __restrict__ Wv,
                             const float4* __restrict__ Wo,
                             const float4* __restrict__ W1) {
    for (int i = blockIdx.x * 256 + threadIdx.x; i < PREP_N4;
         i += gridDim.x * 256) {
        const float4* src; float4* dst;
        if (i < 3 * SEG_EE4) {
            int seg = i / SEG_EE4, off = i - seg * SEG_EE4;
            src = (seg == 0 ? Wq : seg == 1 ? Wk : Wv) + off;
            dst = (float4*)g_wqkv + i;
        } else if (i < 4 * SEG_EE4) {
            src = Wo + (i - 3 * SEG_EE4);
            dst = (float4*)g_wo + (i - 3 * SEG_EE4);
        } else {
            src = W1 + (i - 4 * SEG_EE4);
            dst = (float4*)g_w1 + (i - 4 * SEG_EE4);
        }
        float4 v = *src;
        *dst = make_float4(f2tff(v.x), f2tff(v.y), f2tff(v.z), f2tff(v.w));
    }
}
#define MISC_N (E_*FFP_ + NT_*16 + QKVW)
__global__ void prep_misc(const float* __restrict__ f2w,
                          const float* __restrict__ bq,
                          const float* __restrict__ bk,
                          const float* __restrict__ bv) {
    for (int i = blockIdx.x * 256 + threadIdx.x; i < MISC_N;
         i += gridDim.x * 256) {
        if (i < E_ * FFP_) {
            int r = i / FFP_, c = i - r * FFP_;
            g_w2[i] = c < FF_ ? f2tff(f2w[r * FF_ + c]) : 0.f;
        } else if (i < E_ * FFP_ + NT_ * 16) {
            int j = i - E_ * FFP_;
            int r = j >> 4, c = j & 15;
            g_ff[(size_t)r * FFP_ + FF_ + c] = 0.f;
        } else {
            int j = i - E_ * FFP_ - NT_ * 16;
            g_bqkv[j] = j < E_ ? bq[j] : (j < 2 * E_ ? bk[j - E_] : bv[j - 2 * E_]);
        }
    }
}

// ---------------- RMSNorm (tf32-rounded output) -----------------------------
__global__ void rmsnorm_kernel(const float* __restrict__ x,
                               const float* __restrict__ w,
                               float* __restrict__ out, float eps) {
    int t = blockIdx.x;
    const float* xr = x + (size_t)t * E_;
    float ss = 0.f;
    for (int e = threadIdx.x; e < E_; e += 256) { float v = xr[e]; ss += v * v; }
    __shared__ float red[8];
    #pragma unroll
    for (int o = 16; o > 0; o >>= 1) ss += __shfl_xor_sync(0xffffffffu, ss, o);
    if ((threadIdx.x & 31) == 0) red[threadIdx.x >> 5] = ss;
    __syncthreads();
    if (threadIdx.x < 8) {
        float v = red[threadIdx.x];
        #pragma unroll
        for (int o = 4; o > 0; o >>= 1) v += __shfl_xor_sync(0xffu, v, o);
        if (threadIdx.x == 0) red[0] = v;
    }
    __syncthreads();
    float scale = rsqrtf(red[0] / (float)E_ + eps);
    float* outr = out + (size_t)t * E_;
    for (int e = threadIdx.x; e < E_; e += 256)
        outr[e] = f2tff(xr[e] * scale * w[e]);
}

// ---------------- TF32 GEMM: 256x128 tile, BK=32, 3 stages, 512 thr ---------
#define BKg 32
#define PADg 36
#define STGS 3
#define ASTAGE (256*PADg)
#define BSTAGE (128*PADg)
#define GSMEM ((STGS*(ASTAGE+BSTAGE))*4)

__device__ __forceinline__ void cpa16(unsigned dst, const void* src) {
    asm volatile("cp.async.cg.shared.global [%0], [%1], 16;\n" :: "r"(dst), "l"(src));
}
__device__ __forceinline__ void ldsm4(unsigned& r0, unsigned& r1,
                                      unsigned& r2, unsigned& r3,
                                      const float* p) {
    unsigned a = (unsigned)__cvta_generic_to_shared(p);
    asm volatile("ldmatrix.sync.aligned.m8n8.x4.shared.b16 {%0,%1,%2,%3}, [%4];"
                 : "=r"(r0), "=r"(r1), "=r"(r2), "=r"(r3) : "r"(a));
}
__device__ __forceinline__ void ldsm2(unsigned& r0, unsigned& r1,
                                      const float* p) {
    unsigned a = (unsigned)__cvta_generic_to_shared(p);
    asm volatile("ldmatrix.sync.aligned.m8n8.x2.shared.b16 {%0,%1}, [%2];"
                 : "=r"(r0), "=r"(r1) : "r"(a));
}

#define MMA_TF32(ACC, AF, B0, B1)                                         \
    asm volatile(                                                         \
        "mma.sync.aligned.m16n8k8.row.col.f32.tf32.tf32.f32 "             \
        "{%0,%1,%2,%3}, {%4,%5,%6,%7}, {%8,%9}, {%0,%1,%2,%3};"           \
        : "+f"((ACC)[0]), "+f"((ACC)[1]), "+f"((ACC)[2]), "+f"((ACC)[3])  \
        : "r"((AF)[0]), "r"((AF)[1]), "r"((AF)[2]), "r"((AF)[3]),         \
          "r"(B0), "r"(B1))

template<int GELU, int RES, int RND>
__global__ void __launch_bounds__(512, 1)
gemm256(const float* __restrict__ A, int lda,
        const float* __restrict__ W, const float* __restrict__ bias,
        const float* __restrict__ res, float* __restrict__ C, int ldc,
        int M, int N, int K) {
    extern __shared__ float sm[];
    float* As = sm;
    float* Bs = sm + STGS * ASTAGE;

    int t = threadIdx.x, lane = t & 31, warp = t >> 5;
    int wm = warp & 3, wn = warp >> 2;
    int g = lane >> 2, tg = lane & 3;
    int m0 = blockIdx.y * 256, n0 = blockIdx.x * 128;

    int alr = lane & 15, alc = (lane >> 4) * 4;
    int btile = lane >> 3;
    int blr = (btile >> 1) * 8 + (lane & 7), blc = (btile & 1) * 4;

    int rowA_[4], colA_[4];
    #pragma unroll
    for (int r = 0; r < 4; r++) {
        int c = t + r * 512;
        rowA_[r] = c >> 3; colA_[r] = (c & 7) * 4;
    }
    int rowB_[2], colB_[2], nB_[2];
    #pragma unroll
    for (int r = 0; r < 2; r++) {
        int c = t + r * 512;
        rowB_[r] = c >> 3; colB_[r] = (c & 7) * 4;
        nB_[r] = min(n0 + rowB_[r], N - 1);
    }

    float acc[4][4][4];
    #pragma unroll
    for (int i = 0; i < 4; i++)
        #pragma unroll
        for (int j = 0; j < 4; j++)
            #pragma unroll
            for (int c = 0; c < 4; c++) acc[i][j][c] = 0.f;

    const int KT = K / BKg;

    auto issue = [&](int kt) {
        int st = kt % STGS;
        int kk = kt * BKg;
        unsigned as = (unsigned)__cvta_generic_to_shared(As + st * ASTAGE);
        unsigned bs = (unsigned)__cvta_generic_to_shared(Bs + st * BSTAGE);
        #pragma unroll
        for (int r = 0; r < 4; r++)
            cpa16(as + (rowA_[r] * PADg + colA_[r]) * 4,
                  A + (size_t)(m0 + rowA_[r]) * lda + kk + colA_[r]);
        #pragma unroll
        for (int r = 0; r < 2; r++)
            cpa16(bs + (rowB_[r] * PADg + colB_[r]) * 4,
                  W + (size_t)nB_[r] * K + kk + colB_[r]);
        asm volatile("cp.async.commit_group;\n" ::: "memory");
    };

    issue(0); issue(1);
    asm volatile("cp.async.wait_group 1;\n" ::: "memory");
    __syncthreads();

    for (int kt = 0; kt < KT; kt++) {
        const float* as = As + (kt % STGS) * ASTAGE + (wm * 64 + alr) * PADg + alc;
        const float* bs = Bs + (kt % STGS) * BSTAGE + (wn * 32 + blr) * PADg + blc;
        #pragma unroll
        for (int h = 0; h < 4; h++) {
            int kb = h * 8;
            unsigned af[4][4], bf[2][4];
            #pragma unroll
            for (int mt = 0; mt < 4; mt++)
                ldsm4(af[mt][0], af[mt][1], af[mt][2], af[mt][3],
                      as + mt * 16 * PADg + kb);
            #pragma unroll
            for (int np = 0; np < 2; np++)
                ldsm4(bf[np][0], bf[np][1], bf[np][2], bf[np][3],
                      bs + np * 16 * PADg + kb);
            #pragma unroll
            for (int mt = 0; mt < 4; mt++)
                #pragma unroll
                for (int nt = 0; nt < 4; nt++)
                    MMA_TF32(acc[mt][nt], af[mt],
                             bf[nt >> 1][(nt & 1) * 2], bf[nt >> 1][(nt & 1) * 2 + 1]);
        }

        if (kt + 2 < KT) {
            issue(kt + 2);
            asm volatile("cp.async.wait_group 1;\n" ::: "memory");
        } else {
            asm volatile("cp.async.wait_group 0;\n" ::: "memory");
        }
        __syncthreads();
    }

    #pragma unroll
    for (int mt = 0; mt < 4; mt++) {
        int row0 = m0 + wm * 64 + mt * 16 + g;
        int row1 = row0 + 8;
        #pragma unroll
        for (int nt = 0; nt < 4; nt++) {
            int col = n0 + wn * 32 + nt * 8 + tg * 2;
            if (col < N) {
                float b0 = bias[col], b1 = bias[col + 1];
                float v00 = acc[mt][nt][0] + b0, v01 = acc[mt][nt][1] + b1;
                float v10 = acc[mt][nt][2] + b0, v11 = acc[mt][nt][3] + b1;
                if (GELU) {
                    float u;
                    u = 0.7978845608028654f * (v00 + 0.044715f * v00 * v00 * v00);
                    v00 = 0.5f * v00 * (1.f + tanhf(u));
                    u = 0.7978845608028654f * (v01 + 0.044715f * v01 * v01 * v01);
                    v01 = 0.5f * v01 * (1.f + tanhf(u));
                    u = 0.7978845608028654f * (v10 + 0.044715f * v10 * v10 * v10);
                    v10 = 0.5f * v10 * (1.f + tanhf(u));
                    u = 0.7978845608028654f * (v11 + 0.044715f * v11 * v11 * v11);
                    v11 = 0.5f * v11 * (1.f + tanhf(u));
                }
                if (RES) {
                    v00 += res[(size_t)row0 * ldc + col];
                    v01 += res[(size_t)row0 * ldc + col + 1];
                    v10 += res[(size_t)row1 * ldc + col];
                    v11 += res[(size_t)row1 * ldc + col + 1];
                }
                if (RND) {
                    v00 = f2tff(v00); v01 = f2tff(v01);
                    v10 = f2tff(v10); v11 = f2tff(v11);
                }
                C[(size_t)row0 * ldc + col]     = v00;
                C[(size_t)row0 * ldc + col + 1] = v01;
                C[(size_t)row1 * ldc + col]     = v10;
                C[(size_t)row1 * ldc + col + 1] = v11;
            }
        }
    }
}

// ---------------- Differential attention: pipelined score/PV ----------------
#define KW 44
#define VSTW 260
#define PW 36
#define ATT_SMEM ((256*KW + 72*VSTW + 256*72 + 16*16*PW) * 4)

__global__ void __launch_bounds__(512, 1)
diffattn_mma(const float* __restrict__ qkv,
             const float* __restrict__ lq1, const float* __restrict__ lk1,
             const float* __restrict__ lq2, const float* __restrict__ lk2,
             const float* __restrict__ subw, float* __restrict__ out) {
    extern __shared__ __align__(16) float sma[];
    float* Ks  = sma;
    float* Vst = Ks + 256 * KW;
    float* O0  = Vst + 72 * VSTW;
    float* Pw  = O0 + 256 * 72;

    int b = blockIdx.x >> 4, h = blockIdx.x & 15;
    int tid = threadIdx.x, lane = tid & 31, warp = tid >> 5;
    int g = lane >> 2, tg = lane & 3;
    size_t base = (size_t)b * S_ * QKVW;
    int coff = h * HD_;

    int alr = lane & 15, alc = (lane >> 4) * 4;
    int btile = lane >> 3;
    int blr = (btile >> 1) * 8 + (lane & 7), blc = (btile & 1) * 4;
    int tlr = lane & 7, tlc = ((lane >> 3) & 1) * 4;

    float s1 = 0.f, s2 = 0.f;
    #pragma unroll
    for (int i = 0; i < HD2_; i++) { s1 += lq1[i] * lk1[i]; s2 += lq2[i] * lk2[i]; }
    const float lambda_init = 0.8f - 0.6f * expf(-3.3f);
    const float lambda = expf(s1) - expf(s2) + lambda_init;
    const float oscale = 1.0f - lambda_init;
    const float iscale = rsqrtf(72.f);

    for (int e = tid; e < 256 * 72; e += 512) {
        int s = e / 72, d = e - s * 72;
        Vst[d * VSTW + s] = qkv[base + (size_t)s * QKVW + 2 * E_ + coff + d];
    }

    float* myP = Pw + warp * 16 * PW;
    int qrow0 = warp * 16;

    for (int sub = 0; sub < 2; sub++) {
        __syncthreads();
        for (int e = tid; e < 256 * KW; e += 512) {
            int s = e / KW, kk = e - s * KW;
            Ks[s * KW + kk] = kk < HD2_
                ? qkv[base + (size_t)s * QKVW + E_ + coff + sub * HD2_ + kk] : 0.f;
        }
        __syncthreads();

        unsigned qf[5][4];
        const float* qp = qkv + base + (size_t)qrow0 * QKVW + coff + sub * HD2_;
        #pragma unroll
        for (int kc = 0; kc < 5; kc++) {
            int kb = kc * 8;
            qf[kc][0] = __float_as_uint(qp[(size_t)g * QKVW + kb + tg]);
            qf[kc][1] = __float_as_uint(qp[(size_t)(g + 8) * QKVW + kb + tg]);
            int k4 = kb + tg + 4;
            qf[kc][2] = k4 < HD2_ ? __float_as_uint(qp[(size_t)g * QKVW + k4]) : 0u;
            qf[kc][3] = k4 < HD2_ ? __float_as_uint(qp[(size_t)(g + 8) * QKVW + k4]) : 0u;
        }

        float zr0 = 0.f, zr1 = 0.f;
        float oc[9][4];
        #pragma unroll
        for (int vt = 0; vt < 9; vt++)
            #pragma unroll
            for (int c = 0; c < 4; c++) oc[vt][c] = 0.f;

        // score for a chunk into sc[par]
        float sc[2][4][4];
        auto score = [&](int ch, int par) {
            #pragma unroll
            for (int nt = 0; nt < 4; nt++)
                #pragma unroll
                for (int c = 0; c < 4; c++) sc[par][nt][c] = 0.f;
            const float* kbase = Ks + (ch * 32 + blr) * KW + blc;
            #pragma unroll
            for (int kc = 0; kc < 5; kc++) {
                int kb = kc * 8;
                unsigned bf[2][4];
                #pragma unroll
                for (int half = 0; half < 2; half++)
                    ldsm4(bf[half][0], bf[half][1], bf[half][2], bf[half][3],
                          kbase + half * 16 * KW + kb);
                #pragma unroll
                for (int nt = 0; nt < 4; nt++)
                    MMA_TF32(sc[par][nt], qf[kc],
                             bf[nt >> 1][(nt & 1) * 2],
                             bf[nt >> 1][(nt & 1) * 2 + 1]);
            }
        };

        score(0, 0);
        #pragma unroll
        for (int ch = 0; ch < 8; ch++) {
            int par = ch & 1;
            // exp + stash P for this chunk
            #pragma unroll
            for (int nt = 0; nt < 4; nt++) {
                float e0 = __expf(sc[par][nt][0] * iscale);
                float e1 = __expf(sc[par][nt][1] * iscale);
                float e2 = __expf(sc[par][nt][2] * iscale);
                float e3 = __expf(sc[par][nt][3] * iscale);
                zr0 += e0 + e1;
                zr1 += e2 + e3;
                int c0 = nt * 8 + 2 * tg;
                *(float2*)&myP[g * PW + c0]       = make_float2(f2tff(e0), f2tff(e1));
                *(float2*)&myP[(g + 8) * PW + c0] = make_float2(f2tff(e2), f2tff(e3));
            }
            __syncwarp();

            // prefetch next chunk's scores (independent of P) to overlap w/ PV
            if (ch < 7) score(ch + 1, par ^ 1);

            // PV for this chunk
            #pragma unroll
            for (int kc = 0; kc < 4; kc++) {
                int kb = kc * 8;
                unsigned pa[4];
                ldsm4(pa[0], pa[1], pa[2], pa[3], myP + alr * PW + kb + alc);
                const float* vb0 = Vst + blr * VSTW + ch * 32 + kb + blc;
                #pragma unroll
                for (int g4 = 0; g4 < 4; g4++) {
                    unsigned vb[4];
                    ldsm4(vb[0], vb[1], vb[2], vb[3], vb0 + g4 * 16 * VSTW);
                    MMA_TF32(oc[g4 * 2],     pa, vb[0], vb[1]);
                    MMA_TF32(oc[g4 * 2 + 1], pa, vb[2], vb[3]);
                }
                unsigned t0, t1;
                ldsm2(t0, t1, Vst + (64 + tlr) * VSTW + ch * 32 + kb + tlc);
                MMA_TF32(oc[8], pa, t0, t1);
            }
            __syncwarp();
        }

        zr0 += __shfl_xor_sync(0xffffffffu, zr0, 1);
        zr0 += __shfl_xor_sync(0xffffffffu, zr0, 2);
        zr1 += __shfl_xor_sync(0xffffffffu, zr1, 1);
        zr1 += __shfl_xor_sync(0xffffffffu, zr1, 2);
        float iz0 = 1.f / zr0, iz1 = 1.f / zr1;

        if (sub == 0) {
            #pragma unroll
            for (int vt = 0; vt < 9; vt++) {
                int c0 = vt * 8 + 2 * tg;
                *(float2*)&O0[(qrow0 + g) * 72 + c0] =
                    make_float2(oc[vt][0] * iz0, oc[vt][1] * iz0);
                *(float2*)&O0[(qrow0 + g + 8) * 72 + c0] =
                    make_float2(oc[vt][2] * iz1, oc[vt][3] * iz1);
            }
        } else {
            float cr[9][4];
            float ss0 = 0.f, ss1 = 0.f;
            #pragma unroll
            for (int vt = 0; vt < 9; vt++) {
                int c0 = vt * 8 + 2 * tg;
                float2 p0 = *(const float2*)&O0[(qrow0 + g) * 72 + c0];
                float2 p1 = *(const float2*)&O0[(qrow0 + g + 8) * 72 + c0];
                cr[vt][0] = p0.x - lambda * oc[vt][0] * iz0;
                cr[vt][1] = p0.y - lambda * oc[vt][1] * iz0;
                cr[vt][2] = p1.x - lambda * oc[vt][2] * iz1;
                cr[vt][3] = p1.y - lambda * oc[vt][3] * iz1;
                ss0 += cr[vt][0] * cr[vt][0] + cr[vt][1] * cr[vt][1];
                ss1 += cr[vt][2] * cr[vt][2] + cr[vt][3] * cr[vt][3];
            }
            ss0 += __shfl_xor_sync(0xffffffffu, ss0, 1);
            ss0 += __shfl_xor_sync(0xffffffffu, ss0, 2);
            ss1 += __shfl_xor_sync(0xffffffffu, ss1, 1);
            ss1 += __shfl_xor_sync(0xffffffffu, ss1, 2);
            float sc0 = rsqrtf(ss0 / 72.f + 1e-5f) * oscale;
            float sc1 = rsqrtf(ss1 / 72.f + 1e-5f) * oscale;
            float* o0p = out + (size_t)(b * S_ + qrow0 + g) * E_ + coff;
            float* o1p = out + (size_t)(b * S_ + qrow0 + g + 8) * E_ + coff;
            #pragma unroll
            for (int vt = 0; vt < 9; vt++) {
                int c0 = vt * 8 + 2 * tg;
                float w0 = subw[c0], w1 = subw[c0 + 1];
                *(float2*)&o0p[c0] =
                    make_float2(f2tff(cr[vt][0] * sc0 * w0),
                                f2tff(cr[vt][1] * sc0 * w1));
                *(float2*)&o1p[c0] =
                    make_float2(f2tff(cr[vt][2] * sc1 * w0),
                                f2tff(cr[vt][3] * sc1 * w1));
            }
        }
    }
}

// ---------------- host launch ---------------------------------------------
extern "C" void kernel_launch(void* const* d_in, const int* in_sizes, int n_in,
                              void* d_out, int out_size) {
    const float* hs   = (const float*)d_in[0];
    const float* Wq   = (const float*)d_in[1];
    const float* bq   = (const float*)d_in[2];
    const float* Wk   = (const float*)d_in[3];
    const float* bk   = (const float*)d_in[4];
    const float* Wv   = (const float*)d_in[5];
    const float* bv   = (const float*)d_in[6];
    const float* Wo   = (const float*)d_in[7];
    const float* bo   = (const float*)d_in[8];
    const float* lq1  = (const float*)d_in[9];
    const float* lk1  = (const float*)d_in[10];
    const float* lq2  = (const float*)d_in[11];
    const float* lk2  = (const float*)d_in[12];
    const float* subw = (const float*)d_in[13];
    const float* r1w  = (const float*)d_in[14];
    const float* r2w  = (const float*)d_in[15];
    const float* f1w  = (const float*)d_in[16];
    const float* f1b  = (const float*)d_in[17];
    const float* f2w  = (const float*)d_in[18];
    const float* f2b  = (const float*)d_in[19];

    float *xn, *qkvb, *at, *hb, *yn, *ff;
    float *wqkv, *bqkv, *wo, *w1, *w2;
    cudaGetSymbolAddress((void**)&xn,   g_xn);
    cudaGetSymbolAddress((void**)&qkvb, g_qkv);
    cudaGetSymbolAddress((void**)&at,   g_attn);
    cudaGetSymbolAddress((void**)&hb,   g_h);
    cudaGetSymbolAddress((void**)&yn,   g_yn);
    cudaGetSymbolAddress((void**)&ff,   g_ff);
    cudaGetSymbolAddress((void**)&wqkv, g_wqkv);
    cudaGetSymbolAddress((void**)&bqkv, g_bqkv);
    cudaGetSymbolAddress((void**)&wo,   g_wo);
    cudaGetSymbolAddress((void**)&w1,   g_w1);
    cudaGetSymbolAddress((void**)&w2,   g_w2);

    cudaFuncSetAttribute(diffattn_mma,
                         cudaFuncAttributeMaxDynamicSharedMemorySize, ATT_SMEM);
    cudaFuncSetAttribute(gemm256<0,0,1>,
                         cudaFuncAttributeMaxDynamicSharedMemorySize, GSMEM);
    cudaFuncSetAttribute(gemm256<0,1,0>,
                         cudaFuncAttributeMaxDynamicSharedMemorySize, GSMEM);
    cudaFuncSetAttribute(gemm256<1,0,1>,
                         cudaFuncAttributeMaxDynamicSharedMemorySize, GSMEM);

    prep_weights<<<1184, 256>>>((const float4*)Wq, (const float4*)Wk,
                                (const float4*)Wv, (const float4*)Wo,
                                (const float4*)f1w);
    prep_misc<<<1184, 256>>>(f2w, bq, bk, bv);

    dim3 gqkv(27, 32), g9(9, 32), g34(34, 32);

    rmsnorm_kernel<<<NT_, 256>>>(hs, r1w, xn, 1e-6f);
    gemm256<0,0,1><<<gqkv, 512, GSMEM>>>(xn, E_, wqkv, bqkv, nullptr,
                                         qkvb, QKVW, NT_, QKVW, E_);
    diffattn_mma<<<B_*H_, 512, ATT_SMEM>>>(qkvb, lq1, lk1, lq2, lk2, subw, at);
    gemm256<0,1,0><<<g9, 512, GSMEM>>>(at, E_, wo, bo, hs, hb, E_, NT_, E_, E_);
    rmsnorm_kernel<<<NT_, 256>>>(hb, r2w, yn, 1e-6f);
    gemm256<1,0,1><<<g34, 512, GSMEM>>>(yn, E_, w1, f1b, nullptr, ff, FFP_,
                                        NT_, FF_, E_);
    gemm256<0,1,0><<<g9, 512, GSMEM>>>(ff, FFP_, w2, f2b, hb, (float*)d_out, E_,
                                       NT_, E_, FFP_);
}

// round 17
// speedup vs baseline: 1.0903x; 1.0120x over previous
#include <cuda_runtime.h>
#include <math.h>

#define E_   1152
#define H_   16
#define HD_  72
#define HD2_ 36
#define FF_  4304
#define FFP_ 4320
#define B_   32
#define S_   256
#define NT_  (B_*S_)
#define QKVW 3456

// ---------------- scratch --------------------------------------------------
__device__ float g_xn  [NT_*E_];
__device__ float g_qkv [NT_*QKVW];
__device__ float g_attn[NT_*E_];
__device__ float g_h   [NT_*E_];
__device__ float g_yn  [NT_*E_];
__device__ float g_ff  [NT_*FFP_];
__device__ float g_wqkv[QKVW*E_];
__device__ float g_bqkv[QKVW];
__device__ float g_wo[E_*E_];
__device__ float g_w1[FF_*E_];
__device__ float g_w2[E_*FFP_];

__device__ __forceinline__ unsigned f2tf(float f) {
    unsigned u; asm("cvt.rna.tf32.f32 %0, %1;" : "=r"(u) : "f"(f)); return u;
}
__device__ __forceinline__ float f2tff(float f) {
    return __uint_as_float(f2tf(f));
}

// ---------------- prolog: QKV weights + bias (needed before QKV GEMM) -------
#define SEG_EE4  (E_*E_/4)
#define QKVW4    (QKVW/4)
__global__ void prep_qkvw(const float4* __restrict__ Wq,
                          const float4* __restrict__ Wk,
                          const float4* __restrict__ Wv,
                          const float4* __restrict__ bq,
                          const float4* __restrict__ bk,
                          const float4* __restrict__ bv) {
    int total = 3 * SEG_EE4 + 3 * (E_ / 4);
    for (int i = blockIdx.x * 256 + threadIdx.x; i < total;
         i += gridDim.x * 256) {
        if (i < 3 * SEG_EE4) {
            int seg = i / SEG_EE4, off = i - seg * SEG_EE4;
            float4 v = (seg == 0 ? Wq : seg == 1 ? Wk : Wv)[off];
            ((float4*)g_wqkv)[i] =
                make_float4(f2tff(v.x), f2tff(v.y), f2tff(v.z), f2tff(v.w));
        } else {
            int j = i - 3 * SEG_EE4;           // 0 .. 3*E/4
            int seg = j / (E_ / 4), off = j - seg * (E_ / 4);
            ((float4*)g_bqkv)[seg * (E_ / 4) + off] =
                (seg == 0 ? bq : seg == 1 ? bk : bv)[off];
        }
    }
}

// ---------------- prolog: Wo, W1, W2(+pad), ff-pad (needed before O-proj) ---
__global__ void prep_rest(const float4* __restrict__ Wo,
                          const float4* __restrict__ W1,
                          const float* __restrict__ f2w) {
    int n4 = SEG_EE4 + FF_ * E_ / 4;
    for (int i = blockIdx.x * 256 + threadIdx.x; i < n4;
         i += gridDim.x * 256) {
        float4 v; float4* dst;
        if (i < SEG_EE4) { v = Wo[i]; dst = (float4*)g_wo + i; }
        else             { v = W1[i - SEG_EE4]; dst = (float4*)g_w1 + (i - SEG_EE4); }
        *dst = make_float4(f2tff(v.x), f2tff(v.y), f2tff(v.z), f2tff(v.w));
    }
    int nf = E_ * FFP_ + NT_ * 16;
    for (int i = blockIdx.x * 256 + threadIdx.x; i < nf;
         i += gridDim.x * 256) {
        if (i < E_ * FFP_) {
            int r = i / FFP_, c = i - r * FFP_;
            g_w2[i] = c < FF_ ? f2tff(f2w[r * FF_ + c]) : 0.f;
        } else {
            int j = i - E_ * FFP_;
            int r = j >> 4, c = j & 15;
            g_ff[(size_t)r * FFP_ + FF_ + c] = 0.f;
        }
    }
}

// ---------------- RMSNorm (tf32-rounded output) -----------------------------
__global__ void rmsnorm_kernel(const float* __restrict__ x,
                               const float* __restrict__ w,
                               float* __restrict__ out, float eps) {
    int t = blockIdx.x;
    const float* xr = x + (size_t)t * E_;
    float ss = 0.f;
    for (int e = threadIdx.x; e < E_; e += 256) { float v = xr[e]; ss += v * v; }
    __shared__ float red[8];
    #pragma unroll
    for (int o = 16; o > 0; o >>= 1) ss += __shfl_xor_sync(0xffffffffu, ss, o);
    if ((threadIdx.x & 31) == 0) red[threadIdx.x >> 5] = ss;
    __syncthreads();
    if (threadIdx.x < 8) {
        float v = red[threadIdx.x];
        #pragma unroll
        for (int o = 4; o > 0; o >>= 1) v += __shfl_xor_sync(0xffu, v, o);
        if (threadIdx.x == 0) red[0] = v;
    }
    __syncthreads();
    float scale = rsqrtf(red[0] / (float)E_ + eps);
    float* outr = out + (size_t)t * E_;
    for (int e = threadIdx.x; e < E_; e += 256)
        outr[e] = f2tff(xr[e] * scale * w[e]);
}

// ---------------- TF32 GEMM: 256x128 tile, BK=32, 3 stages, 512 thr ---------
#define BKg 32
#define PADg 36
#define STGS 3
#define ASTAGE (256*PADg)
#define BSTAGE (128*PADg)
#define GSMEM ((STGS*(ASTAGE+BSTAGE))*4)

__device__ __forceinline__ void cpa16(unsigned dst, const void* src) {
    asm volatile("cp.async.cg.shared.global [%0], [%1], 16;\n" :: "r"(dst), "l"(src));
}
__device__ __forceinline__ void ldsm4(unsigned& r0, unsigned& r1,
                                      unsigned& r2, unsigned& r3,
                                      const float* p) {
    unsigned a = (unsigned)__cvta_generic_to_shared(p);
    asm volatile("ldmatrix.sync.aligned.m8n8.x4.shared.b16 {%0,%1,%2,%3}, [%4];"
                 : "=r"(r0), "=r"(r1), "=r"(r2), "=r"(r3) : "r"(a));
}
__device__ __forceinline__ void ldsm2(unsigned& r0, unsigned& r1,
                                      const float* p) {
    unsigned a = (unsigned)__cvta_generic_to_shared(p);
    asm volatile("ldmatrix.sync.aligned.m8n8.x2.shared.b16 {%0,%1}, [%2];"
                 : "=r"(r0), "=r"(r1) : "r"(a));
}

#define MMA_TF32(ACC, AF, B0, B1)                                         \
    asm volatile(                                                         \
        "mma.sync.aligned.m16n8k8.row.col.f32.tf32.tf32.f32 "             \
        "{%0,%1,%2,%3}, {%4,%5,%6,%7}, {%8,%9}, {%0,%1,%2,%3};"           \
        : "+f"((ACC)[0]), "+f"((ACC)[1]), "+f"((ACC)[2]), "+f"((ACC)[3])  \
        : "r"((AF)[0]), "r"((AF)[1]), "r"((AF)[2]), "r"((AF)[3]),         \
          "r"(B0), "r"(B1))

template<int GELU, int RES, int RND>
__global__ void __launch_bounds__(512, 1)
gemm256(const float* __restrict__ A, int lda,
        const float* __restrict__ W, const float* __restrict__ bias,
        const float* __restrict__ res, float* __restrict__ C, int ldc,
        int M, int N, int K) {
    extern __shared__ float sm[];
    float* As = sm;
    float* Bs = sm + STGS * ASTAGE;

    int t = threadIdx.x, lane = t & 31, warp = t >> 5;
    int wm = warp & 3, wn = warp >> 2;
    int g = lane >> 2, tg = lane & 3;
    int m0 = blockIdx.y * 256, n0 = blockIdx.x * 128;

    int alr = lane & 15, alc = (lane >> 4) * 4;
    int btile = lane >> 3;
    int blr = (btile >> 1) * 8 + (lane & 7), blc = (btile & 1) * 4;

    int rowA_[4], colA_[4];
    #pragma unroll
    for (int r = 0; r < 4; r++) {
        int c = t + r * 512;
        rowA_[r] = c >> 3; colA_[r] = (c & 7) * 4;
    }
    int rowB_[2], colB_[2], nB_[2];
    #pragma unroll
    for (int r = 0; r < 2; r++) {
        int c = t + r * 512;
        rowB_[r] = c >> 3; colB_[r] = (c & 7) * 4;
        nB_[r] = min(n0 + rowB_[r], N - 1);
    }

    float acc[4][4][4];
    #pragma unroll
    for (int i = 0; i < 4; i++)
        #pragma unroll
        for (int j = 0; j < 4; j++)
            #pragma unroll
            for (int c = 0; c < 4; c++) acc[i][j][c] = 0.f;

    const int KT = K / BKg;

    auto issue = [&](int kt) {
        int st = kt % STGS;
        int kk = kt * BKg;
        unsigned as = (unsigned)__cvta_generic_to_shared(As + st * ASTAGE);
        unsigned bs = (unsigned)__cvta_generic_to_shared(Bs + st * BSTAGE);
        #pragma unroll
        for (int r = 0; r < 4; r++)
            cpa16(as + (rowA_[r] * PADg + colA_[r]) * 4,
                  A + (size_t)(m0 + rowA_[r]) * lda + kk + colA_[r]);
        #pragma unroll
        for (int r = 0; r < 2; r++)
            cpa16(bs + (rowB_[r] * PADg + colB_[r]) * 4,
                  W + (size_t)nB_[r] * K + kk + colB_[r]);
        asm volatile("cp.async.commit_group;\n" ::: "memory");
    };

    issue(0); issue(1);
    asm volatile("cp.async.wait_group 1;\n" ::: "memory");
    __syncthreads();

    for (int kt = 0; kt < KT; kt++) {
        const float* as = As + (kt % STGS) * ASTAGE + (wm * 64 + alr) * PADg + alc;
        const float* bs = Bs + (kt % STGS) * BSTAGE + (wn * 32 + blr) * PADg + blc;
        #pragma unroll
        for (int h = 0; h < 4; h++) {
            int kb = h * 8;
            unsigned af[4][4], bf[2][4];
            #pragma unroll
            for (int mt = 0; mt < 4; mt++)
                ldsm4(af[mt][0], af[mt][1], af[mt][2], af[mt][3],
                      as + mt * 16 * PADg + kb);
            #pragma unroll
            for (int np = 0; np < 2; np++)
                ldsm4(bf[np][0], bf[np][1], bf[np][2], bf[np][3],
                      bs + np * 16 * PADg + kb);
            #pragma unroll
            for (int mt = 0; mt < 4; mt++)
                #pragma unroll
                for (int nt = 0; nt < 4; nt++)
                    MMA_TF32(acc[mt][nt], af[mt],
                             bf[nt >> 1][(nt & 1) * 2], bf[nt >> 1][(nt & 1) * 2 + 1]);
        }

        if (kt + 2 < KT) {
            issue(kt + 2);
            asm volatile("cp.async.wait_group 1;\n" ::: "memory");
        } else {
            asm volatile("cp.async.wait_group 0;\n" ::: "memory");
        }
        __syncthreads();
    }

    #pragma unroll
    for (int mt = 0; mt < 4; mt++) {
        int row0 = m0 + wm * 64 + mt * 16 + g;
        int row1 = row0 + 8;
        #pragma unroll
        for (int nt = 0; nt < 4; nt++) {
            int col = n0 + wn * 32 + nt * 8 + tg * 2;
            if (col < N) {
                float b0 = bias[col], b1 = bias[col + 1];
                float v00 = acc[mt][nt][0] + b0, v01 = acc[mt][nt][1] + b1;
                float v10 = acc[mt][nt][2] + b0, v11 = acc[mt][nt][3] + b1;
                if (GELU) {
                    float u;
                    u = 0.7978845608028654f * (v00 + 0.044715f * v00 * v00 * v00);
                    v00 = 0.5f * v00 * (1.f + tanhf(u));
                    u = 0.7978845608028654f * (v01 + 0.044715f * v01 * v01 * v01);
                    v01 = 0.5f * v01 * (1.f + tanhf(u));
                    u = 0.7978845608028654f * (v10 + 0.044715f * v10 * v10 * v10);
                    v10 = 0.5f * v10 * (1.f + tanhf(u));
                    u = 0.7978845608028654f * (v11 + 0.044715f * v11 * v11 * v11);
                    v11 = 0.5f * v11 * (1.f + tanhf(u));
                }
                if (RES) {
                    v00 += res[(size_t)row0 * ldc + col];
                    v01 += res[(size_t)row0 * ldc + col + 1];
                    v10 += res[(size_t)row1 * ldc + col];
                    v11 += res[(size_t)row1 * ldc + col + 1];
                }
                if (RND) {
                    v00 = f2tff(v00); v01 = f2tff(v01);
                    v10 = f2tff(v10); v11 = f2tff(v11);
                }
                C[(size_t)row0 * ldc + col]     = v00;
                C[(size_t)row0 * ldc + col + 1] = v01;
                C[(size_t)row1 * ldc + col]     = v10;
                C[(size_t)row1 * ldc + col + 1] = v11;
            }
        }
    }
}

// ---------------- Differential attention: no-max softmax --------------------
#define KW 44
#define VSTW 260
#define PW 36
#define ATT_SMEM ((256*KW + 72*VSTW + 256*72 + 16*16*PW) * 4)

__global__ void __launch_bounds__(512, 1)
diffattn_mma(const float* __restrict__ qkv,
             const float* __restrict__ lq1, const float* __restrict__ lk1,
             const float* __restrict__ lq2, const float* __restrict__ lk2,
             const float* __restrict__ subw, float* __restrict__ out) {
    extern __shared__ __align__(16) float sma[];
    float* Ks  = sma;
    float* Vst = Ks + 256 * KW;
    float* O0  = Vst + 72 * VSTW;
    float* Pw  = O0 + 256 * 72;

    int b = blockIdx.x >> 4, h = blockIdx.x & 15;
    int tid = threadIdx.x, lane = tid & 31, warp = tid >> 5;
    int g = lane >> 2, tg = lane & 3;
    size_t base = (size_t)b * S_ * QKVW;
    int coff = h * HD_;

    int alr = lane & 15, alc = (lane >> 4) * 4;
    int btile = lane >> 3;
    int blr = (btile >> 1) * 8 + (lane & 7), blc = (btile & 1) * 4;
    int tlr = lane & 7, tlc = ((lane >> 3) & 1) * 4;

    float s1 = 0.f, s2 = 0.f;
    #pragma unroll
    for (int i = 0; i < HD2_; i++) { s1 += lq1[i] * lk1[i]; s2 += lq2[i] * lk2[i]; }
    const float lambda_init = 0.8f - 0.6f * expf(-3.3f);
    const float lambda = expf(s1) - expf(s2) + lambda_init;
    const float oscale = 1.0f - lambda_init;
    const float iscale = rsqrtf(72.f);

    for (int e = tid; e < 256 * 72; e += 512) {
        int s = e / 72, d = e - s * 72;
        Vst[d * VSTW + s] = qkv[base + (size_t)s * QKVW + 2 * E_ + coff + d];
    }

    float* myP = Pw + warp * 16 * PW;
    int qrow0 = warp * 16;

    for (int sub = 0; sub < 2; sub++) {
        __syncthreads();
        for (int e = tid; e < 256 * KW; e += 512) {
            int s = e / KW, kk = e - s * KW;
            Ks[s * KW + kk] = kk < HD2_
                ? qkv[base + (size_t)s * QKVW + E_ + coff + sub * HD2_ + kk] : 0.f;
        }
        __syncthreads();

        unsigned qf[5][4];
        const float* qp = qkv + base + (size_t)qrow0 * QKVW + coff + sub * HD2_;
        #pragma unroll
        for (int kc = 0; kc < 5; kc++) {
            int kb = kc * 8;
            qf[kc][0] = __float_as_uint(qp[(size_t)g * QKVW + kb + tg]);
            qf[kc][1] = __float_as_uint(qp[(size_t)(g + 8) * QKVW + kb + tg]);
            int k4 = kb + tg + 4;
            qf[kc][2] = k4 < HD2_ ? __float_as_uint(qp[(size_t)g * QKVW + k4]) : 0u;
            qf[kc][3] = k4 < HD2_ ? __float_as_uint(qp[(size_t)(g + 8) * QKVW + k4]) : 0u;
        }

        float zr0 = 0.f, zr1 = 0.f;
        float oc[9][4];
        #pragma unroll
        for (int vt = 0; vt < 9; vt++)
            #pragma unroll
            for (int c = 0; c < 4; c++) oc[vt][c] = 0.f;

        for (int ch = 0; ch < 8; ch++) {
            float sc[4][4];
            #pragma unroll
            for (int nt = 0; nt < 4; nt++)
                #pragma unroll
                for (int c = 0; c < 4; c++) sc[nt][c] = 0.f;

            const float* kbase = Ks + (ch * 32 + blr) * KW + blc;
            #pragma unroll
            for (int kc = 0; kc < 5; kc++) {
                int kb = kc * 8;
                unsigned bf[2][4];
                #pragma unroll
                for (int half = 0; half < 2; half++)
                    ldsm4(bf[half][0], bf[half][1], bf[half][2], bf[half][3],
                          kbase + half * 16 * KW + kb);
                #pragma unroll
                for (int nt = 0; nt < 4; nt++)
                    MMA_TF32(sc[nt], qf[kc],
                             bf[nt >> 1][(nt & 1) * 2],
                             bf[nt >> 1][(nt & 1) * 2 + 1]);
            }

            #pragma unroll
            for (int nt = 0; nt < 4; nt++) {
                float e0 = __expf(sc[nt][0] * iscale);
                float e1 = __expf(sc[nt][1] * iscale);
                float e2 = __expf(sc[nt][2] * iscale);
                float e3 = __expf(sc[nt][3] * iscale);
                zr0 += e0 + e1;
                zr1 += e2 + e3;
                int c0 = nt * 8 + 2 * tg;
                *(float2*)&myP[g * PW + c0]       = make_float2(f2tff(e0), f2tff(e1));
                *(float2*)&myP[(g + 8) * PW + c0] = make_float2(f2tff(e2), f2tff(e3));
            }
            __syncwarp();

            #pragma unroll
            for (int kc = 0; kc < 4; kc++) {
                int kb = kc * 8;
                unsigned pa[4];
                ldsm4(pa[0], pa[1], pa[2], pa[3], myP + alr * PW + kb + alc);
                const float* vb0 = Vst + blr * VSTW + ch * 32 + kb + blc;
                #pragma unroll
                for (int g4 = 0; g4 < 4; g4++) {
                    unsigned vb[4];
                    ldsm4(vb[0], vb[1], vb[2], vb[3], vb0 + g4 * 16 * VSTW);
                    MMA_TF32(oc[g4 * 2],     pa, vb[0], vb[1]);
                    MMA_TF32(oc[g4 * 2 + 1], pa, vb[2], vb[3]);
                }
                unsigned t0, t1;
                ldsm2(t0, t1, Vst + (64 + tlr) * VSTW + ch * 32 + kb + tlc);
                MMA_TF32(oc[8], pa, t0, t1);
            }
            __syncwarp();
        }

        zr0 += __shfl_xor_sync(0xffffffffu, zr0, 1);
        zr0 += __shfl_xor_sync(0xffffffffu, zr0, 2);
        zr1 += __shfl_xor_sync(0xffffffffu, zr1, 1);
        zr1 += __shfl_xor_sync(0xffffffffu, zr1, 2);
        float iz0 = 1.f / zr0, iz1 = 1.f / zr1;

        if (sub == 0) {
            #pragma unroll
            for (int vt = 0; vt < 9; vt++) {
                int c0 = vt * 8 + 2 * tg;
                *(float2*)&O0[(qrow0 + g) * 72 + c0] =
                    make_float2(oc[vt][0] * iz0, oc[vt][1] * iz0);
                *(float2*)&O0[(qrow0 + g + 8) * 72 + c0] =
                    make_float2(oc[vt][2] * iz1, oc[vt][3] * iz1);
            }
        } else {
            float cr[9][4];
            float ss0 = 0.f, ss1 = 0.f;
            #pragma unroll
            for (int vt = 0; vt < 9; vt++) {
                int c0 = vt * 8 + 2 * tg;
                float2 p0 = *(const float2*)&O0[(qrow0 + g) * 72 + c0];
                float2 p1 = *(const float2*)&O0[(qrow0 + g + 8) * 72 + c0];
                cr[vt][0] = p0.x - lambda * oc[vt][0] * iz0;
                cr[vt][1] = p0.y - lambda * oc[vt][1] * iz0;
                cr[vt][2] = p1.x - lambda * oc[vt][2] * iz1;
                cr[vt][3] = p1.y - lambda * oc[vt][3] * iz1;
                ss0 += cr[vt][0] * cr[vt][0] + cr[vt][1] * cr[vt][1];
                ss1 += cr[vt][2] * cr[vt][2] + cr[vt][3] * cr[vt][3];
            }
            ss0 += __shfl_xor_sync(0xffffffffu, ss0, 1);
            ss0 += __shfl_xor_sync(0xffffffffu, ss0, 2);
            ss1 += __shfl_xor_sync(0xffffffffu, ss1, 1);
            ss1 += __shfl_xor_sync(0xffffffffu, ss1, 2);
            float sc0 = rsqrtf(ss0 / 72.f + 1e-5f) * oscale;
            float sc1 = rsqrtf(ss1 / 72.f + 1e-5f) * oscale;
            float* o0p = out + (size_t)(b * S_ + qrow0 + g) * E_ + coff;
            float* o1p = out + (size_t)(b * S_ + qrow0 + g + 8) * E_ + coff;
            #pragma unroll
            for (int vt = 0; vt < 9; vt++) {
                int c0 = vt * 8 + 2 * tg;
                float w0 = subw[c0], w1 = subw[c0 + 1];
                *(float2*)&o0p[c0] =
                    make_float2(f2tff(cr[vt][0] * sc0 * w0),
                                f2tff(cr[vt][1] * sc0 * w1));
                *(float2*)&o1p[c0] =
                    make_float2(f2tff(cr[vt][2] * sc1 * w0),
                                f2tff(cr[vt][3] * sc1 * w1));
            }
        }
    }
}

// ---------------- host launch ---------------------------------------------
extern "C" void kernel_launch(void* const* d_in, const int* in_sizes, int n_in,
                              void* d_out, int out_size) {
    const float* hs   = (const float*)d_in[0];
    const float* Wq   = (const float*)d_in[1];
    const float* bq   = (const float*)d_in[2];
    const float* Wk   = (const float*)d_in[3];
    const float* bk   = (const float*)d_in[4];
    const float* Wv   = (const float*)d_in[5];
    const float* bv   = (const float*)d_in[6];
    const float* Wo   = (const float*)d_in[7];
    const float* bo   = (const float*)d_in[8];
    const float* lq1  = (const float*)d_in[9];
    const float* lk1  = (const float*)d_in[10];
    const float* lq2  = (const float*)d_in[11];
    const float* lk2  = (const float*)d_in[12];
    const float* subw = (const float*)d_in[13];
    const float* r1w  = (const float*)d_in[14];
    const float* r2w  = (const float*)d_in[15];
    const float* f1w  = (const float*)d_in[16];
    const float* f1b  = (const float*)d_in[17];
    const float* f2w  = (const float*)d_in[18];
    const float* f2b  = (const float*)d_in[19];

    float *xn, *qkvb, *at, *hb, *yn, *ff;
    float *wqkv, *bqkv, *wo, *w1, *w2;
    cudaGetSymbolAddress((void**)&xn,   g_xn);
    cudaGetSymbolAddress((void**)&qkvb, g_qkv);
    cudaGetSymbolAddress((void**)&at,   g_attn);
    cudaGetSymbolAddress((void**)&hb,   g_h);
    cudaGetSymbolAddress((void**)&yn,   g_yn);
    cudaGetSymbolAddress((void**)&ff,   g_ff);
    cudaGetSymbolAddress((void**)&wqkv, g_wqkv);
    cudaGetSymbolAddress((void**)&bqkv, g_bqkv);
    cudaGetSymbolAddress((void**)&wo,   g_wo);
    cudaGetSymbolAddress((void**)&w1,   g_w1);
    cudaGetSymbolAddress((void**)&w2,   g_w2);

    cudaFuncSetAttribute(diffattn_mma,
                         cudaFuncAttributeMaxDynamicSharedMemorySize, ATT_SMEM);
    cudaFuncSetAttribute(gemm256<0,0,1>,
                         cudaFuncAttributeMaxDynamicSharedMemorySize, GSMEM);
    cudaFuncSetAttribute(gemm256<0,1,0>,
                         cudaFuncAttributeMaxDynamicSharedMemorySize, GSMEM);
    cudaFuncSetAttribute(gemm256<1,0,1>,
                         cudaFuncAttributeMaxDynamicSharedMemorySize, GSMEM);

    // fork two side streams for weight prep, overlap with the main chain
    cudaStream_t sQ, sR;
    cudaStreamCreateWithFlags(&sQ, cudaStreamNonBlocking);
    cudaStreamCreateWithFlags(&sR, cudaStreamNonBlocking);
    cudaEvent_t evRoot, evQ, evR;
    cudaEventCreateWithFlags(&evRoot, cudaEventDisableTiming);
    cudaEventCreateWithFlags(&evQ,    cudaEventDisableTiming);
    cudaEventCreateWithFlags(&evR,    cudaEventDisableTiming);

    cudaEventRecord(evRoot, 0);
    cudaStreamWaitEvent(sQ, evRoot, 0);
    cudaStreamWaitEvent(sR, evRoot, 0);

    prep_qkvw<<<1184, 256, 0, sQ>>>((const float4*)Wq, (const float4*)Wk,
                                    (const float4*)Wv, (const float4*)bq,
                                    (const float4*)bk, (const float4*)bv);
    cudaEventRecord(evQ, sQ);
    prep_rest<<<1184, 256, 0, sR>>>((const float4*)Wo, (const float4*)f1w, f2w);
    cudaEventRecord(evR, sR);

    dim3 gqkv(27, 32), g9(9, 32), g34(34, 32);

    rmsnorm_kernel<<<NT_, 256>>>(hs, r1w, xn, 1e-6f);
    cudaStreamWaitEvent(0, evQ, 0);
    gemm256<0,0,1><<<gqkv, 512, GSMEM>>>(xn, E_, wqkv, bqkv, nullptr,
                                         qkvb, QKVW, NT_, QKVW, E_);
    diffattn_mma<<<B_*H_, 512, ATT_SMEM>>>(qkvb, lq1, lk1, lq2, lk2, subw, at);
    cudaStreamWaitEvent(0, evR, 0);
    gemm256<0,1,0><<<g9, 512, GSMEM>>>(at, E_, wo, bo, hs, hb, E_, NT_, E_, E_);
    rmsnorm_kernel<<<NT_, 256>>>(hb, r2w, yn, 1e-6f);
    gemm256<1,0,1><<<g34, 512, GSMEM>>>(yn, E_, w1, f1b, nullptr, ff, FFP_,
                                        NT_, FF_, E_);
    gemm256<0,1,0><<<g9, 512, GSMEM>>>(ff, FFP_, w2, f2b, hb, (float*)d_out, E_,
                                       NT_, E_, FFP_);

    cudaEventDestroy(evRoot);
    cudaEventDestroy(evQ);
    cudaEventDestroy(evR);
    cudaStreamDestroy(sQ);
    cudaStreamDestroy(sR);
}